// round 7
// baseline (speedup 1.0000x reference)
#include <cuda_runtime.h>
#include <cuda_bf16.h>
#include <math.h>

#define OUTN 11008
#define INN  4096
#define MTOK 4096            // 2 * 2048 tokens
#define NTOT 45088768        // OUTN * INN
#define NCNT 1024
#define SPADU 40             // smem row stride in b16 units (64B data + 16B pad)

// ---------------- scratch (static device globals; no allocation) ----------------
__device__ float          g_wt[NTOT];          // transformed/clipped weights (fp32)
__device__ signed char    g_wq8[NTOT];         // int4-valued weights as int8
__device__ signed char    g_xq8[MTOK * INN];   // int8 activations q
__device__ signed char    g_xq8T[INN * MTOK];  // transposed activations [k][m]
__device__ float          g_corr[NTOT];        // outlier correction [n][m]
__device__ unsigned short g_spk[NTOT];         // per-row sparse k indices
__device__ float          g_spd[NTOT];         // per-row sparse deltas
__device__ int            g_spcnt[OUTN];
__device__ float          g_wscale[OUTN];
__device__ float          g_ascale[MTOK];
__device__ float          g_rowabs[OUTN];
__device__ double         g_psum[OUTN];
__device__ double         g_psumsq[OUTN];
__device__ int            g_pcnt[NCNT];
__device__ float          g_stats[4];          // [0]=mean, [1]=T=3*std, [2]=is_like

// ---------------- K0: kronecker transform + clip + row stats ----------------
__global__ __launch_bounds__(256) void k_transform(
    const float* __restrict__ W, const float* __restrict__ L,
    const float* __restrict__ R, const float* __restrict__ cmax,
    const float* __restrict__ cmin)
{
    __shared__ double sAd[2048];
    __shared__ float  sL[4096];
    __shared__ float  sR[4096];
    float* sA = (float*)sAd;

    const int o   = blockIdx.x;
    const int tid = threadIdx.x;
    const int u   = tid >> 4;
    const int v   = tid & 15;

    const float* Wo = W + (size_t)o * INN;
    for (int i = tid; i < 4096; i += 256) { sA[i] = Wo[i]; sL[i] = L[i]; sR[i] = R[i]; }
    __syncthreads();

    float acc[4][4];
    #pragma unroll
    for (int j = 0; j < 4; j++)
        #pragma unroll
        for (int l = 0; l < 4; l++) acc[j][l] = 0.f;

    for (int b = 0; b < 64; b++) {
        float4 rr = *(const float4*)&sR[(b << 6) + (v << 2)];
        float  wr[4];
        #pragma unroll
        for (int j = 0; j < 4; j++) wr[j] = sA[(((u << 2) + j) << 6) + b];
        #pragma unroll
        for (int j = 0; j < 4; j++) {
            acc[j][0] = fmaf(wr[j], rr.x, acc[j][0]);
            acc[j][1] = fmaf(wr[j], rr.y, acc[j][1]);
            acc[j][2] = fmaf(wr[j], rr.z, acc[j][2]);
            acc[j][3] = fmaf(wr[j], rr.w, acc[j][3]);
        }
    }
    __syncthreads();
    #pragma unroll
    for (int j = 0; j < 4; j++)
        *(float4*)&sA[(((u << 2) + j) << 6) + (v << 2)] =
            make_float4(acc[j][0], acc[j][1], acc[j][2], acc[j][3]);
    __syncthreads();

    float vv[4][4];
    #pragma unroll
    for (int j = 0; j < 4; j++)
        #pragma unroll
        for (int l = 0; l < 4; l++) vv[j][l] = 0.f;

    for (int a = 0; a < 64; a++) {
        float4 td = *(const float4*)&sA[(a << 6) + (v << 2)];
        float4 lc = *(const float4*)&sL[(a << 6) + (u << 2)];
        float lcr[4] = {lc.x, lc.y, lc.z, lc.w};
        #pragma unroll
        for (int j = 0; j < 4; j++) {
            vv[j][0] = fmaf(lcr[j], td.x, vv[j][0]);
            vv[j][1] = fmaf(lcr[j], td.y, vv[j][1]);
            vv[j][2] = fmaf(lcr[j], td.z, vv[j][2]);
            vv[j][3] = fmaf(lcr[j], td.w, vv[j][3]);
        }
    }

    float lmin = 3.4e38f, lmax = -3.4e38f;
    #pragma unroll
    for (int j = 0; j < 4; j++)
        #pragma unroll
        for (int l = 0; l < 4; l++) { lmin = fminf(lmin, vv[j][l]); lmax = fmaxf(lmax, vv[j][l]); }

    __syncthreads();
    sR[tid] = lmin; sR[256 + tid] = lmax;
    __syncthreads();
    for (int s = 128; s > 0; s >>= 1) {
        if (tid < s) {
            sR[tid]       = fminf(sR[tid], sR[tid + s]);
            sR[256 + tid] = fmaxf(sR[256 + tid], sR[256 + tid + s]);
        }
        __syncthreads();
    }
    const float rmin = sR[0], rmax = sR[256];
    const float lo = rmin * (1.f / (1.f + expf(-cmin[o])));
    const float hi = rmax * (1.f / (1.f + expf(-cmax[o])));

    float la = 0.f; double ls = 0.0, lss = 0.0;
    #pragma unroll
    for (int j = 0; j < 4; j++)
        #pragma unroll
        for (int l = 0; l < 4; l++) {
            float w = fminf(fmaxf(vv[j][l], lo), hi);
            vv[j][l] = w;
            la = fmaxf(la, fabsf(w));
            ls += (double)w;
            lss += (double)w * (double)w;
        }

    __syncthreads();
    sAd[tid] = ls; sAd[256 + tid] = lss; sR[tid] = la;
    __syncthreads();
    for (int s = 128; s > 0; s >>= 1) {
        if (tid < s) {
            sAd[tid]       += sAd[tid + s];
            sAd[256 + tid] += sAd[256 + tid + s];
            sR[tid] = fmaxf(sR[tid], sR[tid + s]);
        }
        __syncthreads();
    }
    if (tid == 0) { g_psum[o] = sAd[0]; g_psumsq[o] = sAd[256]; g_rowabs[o] = sR[0]; }

    float* outp = g_wt + (size_t)o * INN;
    #pragma unroll
    for (int j = 0; j < 4; j++)
        *(float4*)&outp[(((u << 2) + j) << 6) + (v << 2)] =
            make_float4(vv[j][0], vv[j][1], vv[j][2], vv[j][3]);
}

// ---------------- K1: reduce per-row partials -> mean, T ----------------
__global__ __launch_bounds__(256) void k_stats1()
{
    __shared__ double ds[512];
    int tid = threadIdx.x;
    double s = 0.0, ss = 0.0;
    for (int i = tid; i < OUTN; i += 256) { s += g_psum[i]; ss += g_psumsq[i]; }
    ds[tid] = s; ds[256 + tid] = ss;
    __syncthreads();
    for (int st = 128; st > 0; st >>= 1) {
        if (tid < st) { ds[tid] += ds[tid + st]; ds[256 + tid] += ds[256 + tid + st]; }
        __syncthreads();
    }
    if (tid == 0) {
        double mean = ds[0] / (double)NTOT;
        double var  = ds[256] / (double)NTOT - mean * mean;
        if (var < 0.0) var = 0.0;
        g_stats[0] = (float)mean;
        g_stats[1] = (float)(3.0 * sqrt(var));
    }
}

// ---------------- K2: outlier count partials ----------------
__global__ __launch_bounds__(256) void k_count()
{
    const float mean = g_stats[0], T = g_stats[1];
    int cnt = 0;
    size_t stride = (size_t)gridDim.x * 256 * 4;
    for (size_t i = ((size_t)blockIdx.x * 256 + threadIdx.x) * 4; i < (size_t)NTOT; i += stride) {
        float4 w4 = *(const float4*)(g_wt + i);
        cnt += (fabsf(w4.x - mean) > T) + (fabsf(w4.y - mean) > T)
             + (fabsf(w4.z - mean) > T) + (fabsf(w4.w - mean) > T);
    }
    __shared__ int sc[256];
    sc[threadIdx.x] = cnt;
    __syncthreads();
    for (int s = 128; s > 0; s >>= 1) {
        if (threadIdx.x < s) sc[threadIdx.x] += sc[threadIdx.x + s];
        __syncthreads();
    }
    if (threadIdx.x == 0) g_pcnt[blockIdx.x] = sc[0];
}

// ---------------- K3: finalize frac -> is_like ----------------
__global__ __launch_bounds__(1024) void k_frac()
{
    __shared__ int sc[NCNT];
    int tid = threadIdx.x;
    sc[tid] = g_pcnt[tid];
    __syncthreads();
    for (int s = 512; s > 0; s >>= 1) {
        if (tid < s) sc[tid] += sc[tid + s];
        __syncthreads();
    }
    if (tid == 0) {
        float frac = (float)sc[0] / (float)NTOT;
        g_stats[2] = (frac > 1e-4f && frac < 0.05f) ? 1.f : 0.f;
    }
}

// ---------------- K4: per-row quantize -> int8 q + sparse (k, delta) list ----------------
__global__ __launch_bounds__(256) void k_wfinal()
{
    __shared__ int scnt[256];
    const int o   = blockIdx.x;
    const int tid = threadIdx.x;
    const float a1 = 0.01f;
    const float T = g_stats[1];
    const bool like = (g_stats[2] != 0.f);

    float ra = g_rowabs[o];
    float m = (like && ra > T) ? (T + (ra - T) * a1) : ra;   // fold monotone in |w|
    float scale = m / 7.0f + 1e-8f;
    if (tid == 0) g_wscale[o] = scale;

    const float* wrow = g_wt + (size_t)o * INN;

    union { int4 v; signed char b[16]; } qpack;
    float dl[16];
    unsigned tagmask = 0;
    int cnt = 0;

    #pragma unroll
    for (int g = 0; g < 4; g++) {
        float4 w4 = *(const float4*)(wrow + tid * 16 + g * 4);
        float wv[4] = {w4.x, w4.y, w4.z, w4.w};
        #pragma unroll
        for (int e = 0; e < 4; e++) {
            int idx = g * 4 + e;
            float w = wv[e];
            bool tg = like && (fabsf(w) > T);
            float win = tg ? copysignf(T + (fabsf(w) - T) * a1, w) : w;
            float q = fminf(fmaxf(rintf(win / scale), -7.f), 7.f);
            float wq = q * scale;
            float wfin = tg ? copysignf(T + (fabsf(wq) - T) / a1, w) : wq;
            qpack.b[idx] = (signed char)q;
            dl[idx] = wfin - wq;       // zero for untagged
            if (tg) { tagmask |= (1u << idx); cnt++; }
        }
    }
    *(int4*)(g_wq8 + (size_t)o * INN + tid * 16) = qpack.v;

    scnt[tid] = cnt;
    __syncthreads();
    for (int s = 1; s < 256; s <<= 1) {
        int v = 0;
        if (tid >= s) v = scnt[tid - s];
        __syncthreads();
        if (tid >= s) scnt[tid] += v;
        __syncthreads();
    }
    int off = scnt[tid] - cnt;
    if (tid == 255) g_spcnt[o] = scnt[255];

    unsigned short* kp = g_spk + (size_t)o * INN;
    float*          dp = g_spd + (size_t)o * INN;
    #pragma unroll
    for (int idx = 0; idx < 16; idx++) {
        if (tagmask & (1u << idx)) {
            kp[off] = (unsigned short)(tid * 16 + idx);
            dp[off] = dl[idx];
            off++;
        }
    }
}

// ---------------- K5: per-token activation fake-quant -> int8 + scale ----------------
__global__ __launch_bounds__(256) void k_actq(const float* __restrict__ X)
{
    __shared__ float red[256];
    int t = blockIdx.x, tid = threadIdx.x;
    const float* x = X + (size_t)t * INN;
    float4 vals[4];
    float la = 0.f;
    #pragma unroll
    for (int i = 0; i < 4; i++) {
        vals[i] = *(const float4*)&x[(tid + i * 256) * 4];
        la = fmaxf(la, fmaxf(fmaxf(fabsf(vals[i].x), fabsf(vals[i].y)),
                             fmaxf(fabsf(vals[i].z), fabsf(vals[i].w))));
    }
    red[tid] = la;
    __syncthreads();
    for (int s = 128; s > 0; s >>= 1) {
        if (tid < s) red[tid] = fmaxf(red[tid], red[tid + s]);
        __syncthreads();
    }
    const float scale = red[0] / 127.0f + 1e-8f;
    if (tid == 0) g_ascale[t] = scale;
    signed char* out = g_xq8 + (size_t)t * INN;
    #pragma unroll
    for (int i = 0; i < 4; i++) {
        float4 v = vals[i];
        union { int w; signed char b[4]; } p;
        p.b[0] = (signed char)fminf(fmaxf(rintf(v.x / scale), -127.f), 127.f);
        p.b[1] = (signed char)fminf(fmaxf(rintf(v.y / scale), -127.f), 127.f);
        p.b[2] = (signed char)fminf(fmaxf(rintf(v.z / scale), -127.f), 127.f);
        p.b[3] = (signed char)fminf(fmaxf(rintf(v.w / scale), -127.f), 127.f);
        *(int*)&out[(tid + i * 256) * 4] = p.w;
    }
}

// ---------------- K5b: transpose activations int8 [m][k] -> [k][m] ----------------
__global__ __launch_bounds__(256) void k_xT()
{
    __shared__ signed char ts[64][65];
    int k0 = blockIdx.x * 64, m0 = blockIdx.y * 64;
    int r  = threadIdx.x >> 2;
    int c4 = (threadIdx.x & 3) * 16;

    union { int4 v; signed char b[16]; } u;
    u.v = *(const int4*)(g_xq8 + (size_t)(m0 + r) * INN + k0 + c4);
    #pragma unroll
    for (int i = 0; i < 16; i++) ts[r][c4 + i] = u.b[i];
    __syncthreads();
    #pragma unroll
    for (int i = 0; i < 16; i++) u.b[i] = ts[c4 + i][r];
    *(int4*)(g_xq8T + (size_t)(k0 + r) * MTOK + m0 + c4) = u.v;
}

// ---------------- K5c: outlier correction corr[n][m] = sum_t qa[m,k_t]*delta_t ----------------
__global__ __launch_bounds__(256) void k_corr()
{
    __shared__ unsigned short sk[512];
    __shared__ float sd[512];
    const int n   = blockIdx.x;
    const int tid = threadIdx.x;
    const int cnt = g_spcnt[n];

    float cv[16];
    #pragma unroll
    for (int i = 0; i < 16; i++) cv[i] = 0.f;

    const unsigned short* kp = g_spk + (size_t)n * INN;
    const float*          dp = g_spd + (size_t)n * INN;

    for (int base = 0; base < cnt; base += 512) {
        int c = cnt - base; if (c > 512) c = 512;
        if (tid < c)       { sk[tid] = kp[base + tid];       sd[tid] = dp[base + tid]; }
        if (tid + 256 < c) { sk[tid + 256] = kp[base + tid + 256]; sd[tid + 256] = dp[base + tid + 256]; }
        __syncthreads();
        for (int t = 0; t < c; t++) {
            const signed char* col = g_xq8T + (size_t)sk[t] * MTOK;
            float d = sd[t];
            #pragma unroll
            for (int i = 0; i < 16; i++)
                cv[i] += (float)col[tid + i * 256] * d;
        }
        __syncthreads();
    }

    float* out = g_corr + (size_t)n * MTOK;
    #pragma unroll
    for (int i = 0; i < 16; i++) out[tid + i * 256] = cv[i];
}

// ---------------- K6: int8 IMMA GEMM (correction folded via g_corr) ----------------
__device__ __forceinline__ void cpasync16(unsigned saddr, const void* g)
{
    asm volatile("cp.async.ca.shared.global [%0], [%1], 16;\n" :: "r"(saddr), "l"(g));
}
__device__ __forceinline__ void ldsm4(unsigned* r, unsigned saddr)
{
    asm volatile("ldmatrix.sync.aligned.m8n8.x4.shared.b16 {%0,%1,%2,%3}, [%4];"
                 : "=r"(r[0]), "=r"(r[1]), "=r"(r[2]), "=r"(r[3]) : "r"(saddr));
}
__device__ __forceinline__ void mma16832(int* d, const unsigned* a, unsigned b0, unsigned b1)
{
    asm volatile("mma.sync.aligned.m16n8k32.row.col.s32.s8.s8.s32 "
                 "{%0,%1,%2,%3}, {%4,%5,%6,%7}, {%8,%9}, {%0,%1,%2,%3};"
                 : "+r"(d[0]), "+r"(d[1]), "+r"(d[2]), "+r"(d[3])
                 : "r"(a[0]), "r"(a[1]), "r"(a[2]), "r"(a[3]), "r"(b0), "r"(b1));
}

__global__ __launch_bounds__(256, 2) void k_gemm_i8(const float* __restrict__ bias,
                                                    float* __restrict__ C)
{
    __shared__ unsigned short sA[2][128 * SPADU];
    __shared__ unsigned short sB[2][128 * SPADU];

    const int tid  = threadIdx.x;
    const int lane = tid & 31;
    const int wid  = tid >> 5;
    const int wm   = wid & 1;       // 2 warps in M
    const int wn   = wid >> 1;      // 4 warps in N
    const int bn   = blockIdx.x * 128;
    const int bm   = blockIdx.y * 128;

    const int lrow  = tid >> 2;          // 0..63
    const int lcolb = (tid & 3) * 16;    // byte col
    const int lcolu = (tid & 3) * 8;     // b16-unit col

    int acc[4][4][4];
    #pragma unroll
    for (int i = 0; i < 4; i++)
        #pragma unroll
        for (int j = 0; j < 4; j++)
            #pragma unroll
            for (int l = 0; l < 4; l++) acc[i][j][l] = 0;

    const signed char* Abase = g_xq8 + (size_t)bm * INN;
    const signed char* Bbase = g_wq8 + (size_t)bn * INN;

    auto load_tile = [&](int it, int buf) {
        int k = it * 64;
        #pragma unroll
        for (int i = 0; i < 2; i++) {
            int row = lrow + i * 64;
            cpasync16((unsigned)__cvta_generic_to_shared(&sA[buf][row * SPADU + lcolu]),
                      Abase + (size_t)row * INN + k + lcolb);
            cpasync16((unsigned)__cvta_generic_to_shared(&sB[buf][row * SPADU + lcolu]),
                      Bbase + (size_t)row * INN + k + lcolb);
        }
    };

    const int KITERS = INN / 64;   // 64
    load_tile(0, 0);
    asm volatile("cp.async.commit_group;\n");

    for (int it = 0; it < KITERS; ++it) {
        int buf = it & 1;
        if (it + 1 < KITERS) {
            load_tile(it + 1, buf ^ 1);
            asm volatile("cp.async.commit_group;\n");
            asm volatile("cp.async.wait_group 1;\n");
        } else {
            asm volatile("cp.async.wait_group 0;\n");
        }
        __syncthreads();

        #pragma unroll
        for (int ks = 0; ks < 2; ks++) {
            unsigned afr[4][4], bfr[2][4];
            int arow = wm * 64 + (lane & 15);
            int acol = ks * 16 + (lane >> 4) * 8;
            #pragma unroll
            for (int mb = 0; mb < 4; mb++)
                ldsm4(afr[mb], (unsigned)__cvta_generic_to_shared(
                          &sA[buf][(arow + mb * 16) * SPADU + acol]));
            int brow = wn * 32 + (lane & 7) + ((lane >> 4) & 1) * 8;
            int bcol = ks * 16 + ((lane >> 3) & 1) * 8;
            #pragma unroll
            for (int nb = 0; nb < 2; nb++)
                ldsm4(bfr[nb], (unsigned)__cvta_generic_to_shared(
                          &sB[buf][(brow + nb * 16) * SPADU + bcol]));
            #pragma unroll
            for (int mb = 0; mb < 4; mb++)
                #pragma unroll
                for (int f = 0; f < 4; f++)
                    mma16832(acc[mb][f], afr[mb],
                             bfr[f >> 1][(f & 1) * 2], bfr[f >> 1][(f & 1) * 2 + 1]);
        }
        __syncthreads();
    }

    // ---- epilogue: out = as_m * (ws_n * acc + corr[n][m]) + bias ----
    #pragma unroll
    for (int mb = 0; mb < 4; mb++) {
        int m0 = bm + wm * 64 + mb * 16 + (lane >> 2);
        float as0 = g_ascale[m0];
        float as1 = g_ascale[m0 + 8];
        #pragma unroll
        for (int f = 0; f < 4; f++) {
            int gn = bn + wn * 32 + f * 8 + (lane & 3) * 2;
            float ws0 = g_wscale[gn], ws1 = g_wscale[gn + 1];
            float b0 = bias[gn], b1 = bias[gn + 1];
            const float* c0 = g_corr + (size_t)gn * MTOK;
            const float* c1 = c0 + MTOK;
            float2 o0 = make_float2(
                as0 * (ws0 * (float)acc[mb][f][0] + c0[m0]) + b0,
                as0 * (ws1 * (float)acc[mb][f][1] + c1[m0]) + b1);
            float2 o1 = make_float2(
                as1 * (ws0 * (float)acc[mb][f][2] + c0[m0 + 8]) + b0,
                as1 * (ws1 * (float)acc[mb][f][3] + c1[m0 + 8]) + b1);
            *(float2*)(C + (size_t)m0 * OUTN + gn)       = o0;
            *(float2*)(C + (size_t)(m0 + 8) * OUTN + gn) = o1;
        }
    }
}

// ---------------- launch ----------------
extern "C" void kernel_launch(void* const* d_in, const int* in_sizes, int n_in,
                              void* d_out, int out_size)
{
    const float* hs   = (const float*)d_in[0];  // (2,2048,4096)
    const float* w    = (const float*)d_in[1];  // (11008,4096)
    const float* bias = (const float*)d_in[2];  // (11008)
    const float* tl   = (const float*)d_in[3];  // (64,64)
    const float* tr   = (const float*)d_in[4];  // (64,64)
    const float* cmax = (const float*)d_in[5];  // (11008,1)
    const float* cmin = (const float*)d_in[6];  // (11008,1)
    float* out = (float*)d_out;

    k_transform<<<OUTN, 256>>>(w, tl, tr, cmax, cmin);
    k_stats1<<<1, 256>>>();
    k_count<<<NCNT, 256>>>();
    k_frac<<<1, 1024>>>();
    k_wfinal<<<OUTN, 256>>>();
    k_actq<<<MTOK, 256>>>(hs);
    dim3 gt(INN / 64, MTOK / 64);
    k_xT<<<gt, 256>>>();
    k_corr<<<OUTN, 256>>>();
    dim3 g(OUTN / 128, MTOK / 128);
    k_gemm_i8<<<g, 256>>>(bias, out);
}

// round 8
// speedup vs baseline: 1.0053x; 1.0053x over previous
#include <cuda_runtime.h>
#include <cuda_bf16.h>
#include <math.h>

#define OUTN 11008
#define INN  4096
#define MTOK 4096            // 2 * 2048 tokens
#define NTOT 45088768        // OUTN * INN
#define SPADU 40             // smem row stride in b16 units (64B data + 16B pad)

// GEMM pipeline config
#define TILEB 10240          // bytes per array per stage (128 rows * 80B)
#define STGB  (2 * TILEB)    // A + B per stage
#define NSTG  4
#define GSMEM (NSTG * STGB)  // 81920

// ---------------- scratch (static device globals; no allocation) ----------------
__device__ float          g_wt[NTOT];          // transformed/clipped weights (fp32)
__device__ signed char    g_wq8[NTOT];         // int4-valued weights as int8
__device__ signed char    g_xq8[MTOK * INN];   // int8 activations q
__device__ signed char    g_xq8T[INN * MTOK];  // transposed activations [k][m]
__device__ float          g_corr[NTOT];        // outlier correction [n][m]
__device__ float          g_wscale[OUTN];
__device__ float          g_ascale[MTOK];
__device__ float          g_rowabs[OUTN];
__device__ double         g_psum[OUTN];
__device__ double         g_psumsq[OUTN];
__device__ int            g_icnt;              // global outlier count (int atomic)
__device__ float          g_stats[4];          // [0]=mean, [1]=T=3*std

// ================ K0: transform (blocks 0..11007) + actq (blocks 11008..15103) ================
__global__ __launch_bounds__(256) void k_front(
    const float* __restrict__ W, const float* __restrict__ L,
    const float* __restrict__ R, const float* __restrict__ cmax,
    const float* __restrict__ cmin, const float* __restrict__ X)
{
    __shared__ double sAd[2048];   // 16KB, aliased as float sA[4096]
    __shared__ float  sL[4096];
    __shared__ float  sR[4096];
    float* sA = (float*)sAd;

    const int tid = threadIdx.x;

    if (blockIdx.x >= OUTN) {
        // ---- activation fake-quant for token t ----
        const int t = blockIdx.x - OUTN;
        if (t == 0 && tid == 0) g_icnt = 0;
        float* red = sL;
        const float* x = X + (size_t)t * INN;
        float4 vals[4];
        float la = 0.f;
        #pragma unroll
        for (int i = 0; i < 4; i++) {
            vals[i] = *(const float4*)&x[(tid + i * 256) * 4];
            la = fmaxf(la, fmaxf(fmaxf(fabsf(vals[i].x), fabsf(vals[i].y)),
                                 fmaxf(fabsf(vals[i].z), fabsf(vals[i].w))));
        }
        red[tid] = la;
        __syncthreads();
        for (int s = 128; s > 0; s >>= 1) {
            if (tid < s) red[tid] = fmaxf(red[tid], red[tid + s]);
            __syncthreads();
        }
        const float scale = red[0] / 127.0f + 1e-8f;
        if (tid == 0) g_ascale[t] = scale;
        signed char* out = g_xq8 + (size_t)t * INN;
        #pragma unroll
        for (int i = 0; i < 4; i++) {
            float4 v = vals[i];
            union { int w; signed char b[4]; } p;
            p.b[0] = (signed char)fminf(fmaxf(rintf(v.x / scale), -127.f), 127.f);
            p.b[1] = (signed char)fminf(fmaxf(rintf(v.y / scale), -127.f), 127.f);
            p.b[2] = (signed char)fminf(fmaxf(rintf(v.z / scale), -127.f), 127.f);
            p.b[3] = (signed char)fminf(fmaxf(rintf(v.w / scale), -127.f), 127.f);
            *(int*)&out[(tid + i * 256) * 4] = p.w;
        }
        return;
    }

    // ---- kronecker transform + clip + row stats for row o ----
    const int o = blockIdx.x;
    const int u = tid >> 4;
    const int v = tid & 15;

    const float* Wo = W + (size_t)o * INN;
    for (int i = tid; i < 4096; i += 256) { sA[i] = Wo[i]; sL[i] = L[i]; sR[i] = R[i]; }
    __syncthreads();

    float acc[4][4];
    #pragma unroll
    for (int j = 0; j < 4; j++)
        #pragma unroll
        for (int l = 0; l < 4; l++) acc[j][l] = 0.f;

    for (int b = 0; b < 64; b++) {
        float4 rr = *(const float4*)&sR[(b << 6) + (v << 2)];
        float  wr[4];
        #pragma unroll
        for (int j = 0; j < 4; j++) wr[j] = sA[(((u << 2) + j) << 6) + b];
        #pragma unroll
        for (int j = 0; j < 4; j++) {
            acc[j][0] = fmaf(wr[j], rr.x, acc[j][0]);
            acc[j][1] = fmaf(wr[j], rr.y, acc[j][1]);
            acc[j][2] = fmaf(wr[j], rr.z, acc[j][2]);
            acc[j][3] = fmaf(wr[j], rr.w, acc[j][3]);
        }
    }
    __syncthreads();
    #pragma unroll
    for (int j = 0; j < 4; j++)
        *(float4*)&sA[(((u << 2) + j) << 6) + (v << 2)] =
            make_float4(acc[j][0], acc[j][1], acc[j][2], acc[j][3]);
    __syncthreads();

    float vv[4][4];
    #pragma unroll
    for (int j = 0; j < 4; j++)
        #pragma unroll
        for (int l = 0; l < 4; l++) vv[j][l] = 0.f;

    for (int a = 0; a < 64; a++) {
        float4 td = *(const float4*)&sA[(a << 6) + (v << 2)];
        float4 lc = *(const float4*)&sL[(a << 6) + (u << 2)];
        float lcr[4] = {lc.x, lc.y, lc.z, lc.w};
        #pragma unroll
        for (int j = 0; j < 4; j++) {
            vv[j][0] = fmaf(lcr[j], td.x, vv[j][0]);
            vv[j][1] = fmaf(lcr[j], td.y, vv[j][1]);
            vv[j][2] = fmaf(lcr[j], td.z, vv[j][2]);
            vv[j][3] = fmaf(lcr[j], td.w, vv[j][3]);
        }
    }

    float lmin = 3.4e38f, lmax = -3.4e38f;
    #pragma unroll
    for (int j = 0; j < 4; j++)
        #pragma unroll
        for (int l = 0; l < 4; l++) { lmin = fminf(lmin, vv[j][l]); lmax = fmaxf(lmax, vv[j][l]); }

    __syncthreads();
    sR[tid] = lmin; sR[256 + tid] = lmax;
    __syncthreads();
    for (int s = 128; s > 0; s >>= 1) {
        if (tid < s) {
            sR[tid]       = fminf(sR[tid], sR[tid + s]);
            sR[256 + tid] = fmaxf(sR[256 + tid], sR[256 + tid + s]);
        }
        __syncthreads();
    }
    const float rmin = sR[0], rmax = sR[256];
    const float lo = rmin * (1.f / (1.f + expf(-cmin[o])));
    const float hi = rmax * (1.f / (1.f + expf(-cmax[o])));

    float la = 0.f; double ls = 0.0, lss = 0.0;
    #pragma unroll
    for (int j = 0; j < 4; j++)
        #pragma unroll
        for (int l = 0; l < 4; l++) {
            float w = fminf(fmaxf(vv[j][l], lo), hi);
            vv[j][l] = w;
            la = fmaxf(la, fabsf(w));
            ls += (double)w;
            lss += (double)w * (double)w;
        }

    __syncthreads();
    sAd[tid] = ls; sAd[256 + tid] = lss; sR[tid] = la;
    __syncthreads();
    for (int s = 128; s > 0; s >>= 1) {
        if (tid < s) {
            sAd[tid]       += sAd[tid + s];
            sAd[256 + tid] += sAd[256 + tid + s];
            sR[tid] = fmaxf(sR[tid], sR[tid + s]);
        }
        __syncthreads();
    }
    if (tid == 0) { g_psum[o] = sAd[0]; g_psumsq[o] = sAd[256]; g_rowabs[o] = sR[0]; }

    float* outp = g_wt + (size_t)o * INN;
    #pragma unroll
    for (int j = 0; j < 4; j++)
        *(float4*)&outp[(((u << 2) + j) << 6) + (v << 2)] =
            make_float4(vv[j][0], vv[j][1], vv[j][2], vv[j][3]);
}

// ================ K1: stats+count (blocks 0..1023) + transpose xT (blocks 1024..5119) ================
__global__ __launch_bounds__(256) void k_mid()
{
    __shared__ double ds[512];
    __shared__ int    sc[256];
    __shared__ signed char ts[64 * 65];

    const int tid = threadIdx.x;

    if (blockIdx.x >= 1024) {
        // ---- int8 transpose [m][k] -> [k][m], 64x64 tile ----
        int b2 = blockIdx.x - 1024;
        int k0 = (b2 & 63) * 64, m0 = (b2 >> 6) * 64;
        int r  = tid >> 2;
        int c4 = (tid & 3) * 16;
        union { int4 v; signed char b[16]; } u;
        u.v = *(const int4*)(g_xq8 + (size_t)(m0 + r) * INN + k0 + c4);
        #pragma unroll
        for (int i = 0; i < 16; i++) ts[r * 65 + c4 + i] = u.b[i];
        __syncthreads();
        #pragma unroll
        for (int i = 0; i < 16; i++) u.b[i] = ts[(c4 + i) * 65 + r];
        *(int4*)(g_xq8T + (size_t)(k0 + r) * MTOK + m0 + c4) = u.v;
        return;
    }

    // ---- every block redundantly reduces row partials -> mean, T ----
    double s = 0.0, ss = 0.0;
    for (int i = tid; i < OUTN; i += 256) { s += g_psum[i]; ss += g_psumsq[i]; }
    ds[tid] = s; ds[256 + tid] = ss;
    __syncthreads();
    for (int st = 128; st > 0; st >>= 1) {
        if (tid < st) { ds[tid] += ds[tid + st]; ds[256 + tid] += ds[256 + tid + st]; }
        __syncthreads();
    }
    double mean_d = ds[0] / (double)NTOT;
    double var    = ds[256] / (double)NTOT - mean_d * mean_d;
    if (var < 0.0) var = 0.0;
    const float mean = (float)mean_d;
    const float T    = (float)(3.0 * sqrt(var));
    if (blockIdx.x == 0 && tid == 0) { g_stats[0] = mean; g_stats[1] = T; }

    // ---- outlier count over this block's slice ----
    int cnt = 0;
    size_t stride = (size_t)1024 * 256 * 4;
    for (size_t i = ((size_t)blockIdx.x * 256 + tid) * 4; i < (size_t)NTOT; i += stride) {
        float4 w4 = *(const float4*)(g_wt + i);
        cnt += (fabsf(w4.x - mean) > T) + (fabsf(w4.y - mean) > T)
             + (fabsf(w4.z - mean) > T) + (fabsf(w4.w - mean) > T);
    }
    sc[tid] = cnt;
    __syncthreads();
    for (int st = 128; st > 0; st >>= 1) {
        if (tid < st) sc[tid] += sc[tid + st];
        __syncthreads();
    }
    if (tid == 0) atomicAdd(&g_icnt, sc[0]);   // int atomic: order-invariant, deterministic
}

// ================ K2: per-row quantize + sparse list (smem) + corr row ================
__global__ __launch_bounds__(256) void k_wfinal2()
{
    __shared__ int            scnt[256];
    __shared__ unsigned short sk[4096];
    __shared__ float          sdl[4096];

    const int o   = blockIdx.x;
    const int tid = threadIdx.x;
    const float a1 = 0.01f;
    const float T = g_stats[1];
    const float frac = (float)g_icnt / (float)NTOT;
    const bool like = (frac > 1e-4f && frac < 0.05f);

    float ra = g_rowabs[o];
    float m = (like && ra > T) ? (T + (ra - T) * a1) : ra;   // fold monotone in |w|
    float scale = m / 7.0f + 1e-8f;
    if (tid == 0) g_wscale[o] = scale;

    const float* wrow = g_wt + (size_t)o * INN;

    union { int4 v; signed char b[16]; } qpack;
    float dl[16];
    unsigned tagmask = 0;
    int cnt = 0;

    #pragma unroll
    for (int g = 0; g < 4; g++) {
        float4 w4 = *(const float4*)(wrow + tid * 16 + g * 4);
        float wv[4] = {w4.x, w4.y, w4.z, w4.w};
        #pragma unroll
        for (int e = 0; e < 4; e++) {
            int idx = g * 4 + e;
            float w = wv[e];
            bool tg = like && (fabsf(w) > T);
            float win = tg ? copysignf(T + (fabsf(w) - T) * a1, w) : w;
            float q = fminf(fmaxf(rintf(win / scale), -7.f), 7.f);
            float wq = q * scale;
            float wfin = tg ? copysignf(T + (fabsf(wq) - T) / a1, w) : wq;
            qpack.b[idx] = (signed char)q;
            dl[idx] = wfin - wq;       // zero for untagged
            if (tg) { tagmask |= (1u << idx); cnt++; }
        }
    }
    *(int4*)(g_wq8 + (size_t)o * INN + tid * 16) = qpack.v;

    // deterministic block-wide exclusive scan
    scnt[tid] = cnt;
    __syncthreads();
    for (int s = 1; s < 256; s <<= 1) {
        int v = 0;
        if (tid >= s) v = scnt[tid - s];
        __syncthreads();
        if (tid >= s) scnt[tid] += v;
        __syncthreads();
    }
    int off = scnt[tid] - cnt;
    __syncthreads();
    const int total = scnt[255];

    #pragma unroll
    for (int idx = 0; idx < 16; idx++) {
        if (tagmask & (1u << idx)) {
            sk[off]  = (unsigned short)(tid * 16 + idx);
            sdl[off] = dl[idx];
            off++;
        }
    }
    __syncthreads();

    // ---- corr[o][m] = sum_t qa[m, k_t] * delta_t ----
    float cv[16];
    #pragma unroll
    for (int i = 0; i < 16; i++) cv[i] = 0.f;
    for (int t = 0; t < total; t++) {
        const signed char* col = g_xq8T + (size_t)sk[t] * MTOK;
        float d = sdl[t];
        #pragma unroll
        for (int i = 0; i < 16; i++)
            cv[i] += (float)col[tid + i * 256] * d;
    }
    float* outc = g_corr + (size_t)o * MTOK;
    #pragma unroll
    for (int i = 0; i < 16; i++) outc[tid + i * 256] = cv[i];
}

// ================ K3: int8 IMMA GEMM, 4-stage cp.async pipeline ================
__device__ __forceinline__ void cpasync16(unsigned saddr, const void* g)
{
    asm volatile("cp.async.ca.shared.global [%0], [%1], 16;\n" :: "r"(saddr), "l"(g));
}
__device__ __forceinline__ void ldsm4(unsigned* r, unsigned saddr)
{
    asm volatile("ldmatrix.sync.aligned.m8n8.x4.shared.b16 {%0,%1,%2,%3}, [%4];"
                 : "=r"(r[0]), "=r"(r[1]), "=r"(r[2]), "=r"(r[3]) : "r"(saddr));
}
__device__ __forceinline__ void mma16832(int* d, const unsigned* a, unsigned b0, unsigned b1)
{
    asm volatile("mma.sync.aligned.m16n8k32.row.col.s32.s8.s8.s32 "
                 "{%0,%1,%2,%3}, {%4,%5,%6,%7}, {%8,%9}, {%0,%1,%2,%3};"
                 : "+r"(d[0]), "+r"(d[1]), "+r"(d[2]), "+r"(d[3])
                 : "r"(a[0]), "r"(a[1]), "r"(a[2]), "r"(a[3]), "r"(b0), "r"(b1));
}

__global__ __launch_bounds__(256, 2) void k_gemm_i8(const float* __restrict__ bias,
                                                    float* __restrict__ C)
{
    extern __shared__ char dsm[];

    const int tid  = threadIdx.x;
    const int lane = tid & 31;
    const int wid  = tid >> 5;
    const int wm   = wid & 1;       // 2 warps in M
    const int wn   = wid >> 1;      // 4 warps in N
    const int bn   = blockIdx.x * 128;
    const int bm   = blockIdx.y * 128;

    const int lrow  = tid >> 2;          // 0..63
    const int lcolb = (tid & 3) * 16;    // byte col
    const int lcolu = (tid & 3) * 8;     // b16-unit col

    int acc[4][4][4];
    #pragma unroll
    for (int i = 0; i < 4; i++)
        #pragma unroll
        for (int j = 0; j < 4; j++)
            #pragma unroll
            for (int l = 0; l < 4; l++) acc[i][j][l] = 0;

    const signed char* Abase = g_xq8 + (size_t)bm * INN;
    const signed char* Bbase = g_wq8 + (size_t)bn * INN;

    auto fill = [&](int it) {
        int s = it & 3;
        int k = it * 64;
        unsigned sA = (unsigned)__cvta_generic_to_shared(dsm + s * STGB);
        unsigned sB = sA + TILEB;
        #pragma unroll
        for (int i = 0; i < 2; i++) {
            int row = lrow + i * 64;
            cpasync16(sA + (row * SPADU + lcolu) * 2, Abase + (size_t)row * INN + k + lcolb);
            cpasync16(sB + (row * SPADU + lcolu) * 2, Bbase + (size_t)row * INN + k + lcolb);
        }
        asm volatile("cp.async.commit_group;\n");
    };

    const int KITERS = INN / 64;   // 64
    fill(0); fill(1); fill(2);

    for (int it = 0; it < KITERS; ++it) {
        if (it < KITERS - 2)      asm volatile("cp.async.wait_group 2;\n");
        else if (it == KITERS - 2) asm volatile("cp.async.wait_group 1;\n");
        else                       asm volatile("cp.async.wait_group 0;\n");
        __syncthreads();

        if (it + 3 < KITERS) fill(it + 3);

        unsigned tb = (unsigned)__cvta_generic_to_shared(dsm + (it & 3) * STGB);
        unsigned tA = tb, tB = tb + TILEB;

        #pragma unroll
        for (int ks = 0; ks < 2; ks++) {
            unsigned afr[4][4], bfr[2][4];
            int arow = wm * 64 + (lane & 15);
            int acol = ks * 16 + (lane >> 4) * 8;
            #pragma unroll
            for (int mb = 0; mb < 4; mb++)
                ldsm4(afr[mb], tA + ((arow + mb * 16) * SPADU + acol) * 2);
            int brow = wn * 32 + (lane & 7) + ((lane >> 4) & 1) * 8;
            int bcol = ks * 16 + ((lane >> 3) & 1) * 8;
            #pragma unroll
            for (int nb = 0; nb < 2; nb++)
                ldsm4(bfr[nb], tB + ((brow + nb * 16) * SPADU + bcol) * 2);
            #pragma unroll
            for (int mb = 0; mb < 4; mb++)
                #pragma unroll
                for (int f = 0; f < 4; f++)
                    mma16832(acc[mb][f], afr[mb],
                             bfr[f >> 1][(f & 1) * 2], bfr[f >> 1][(f & 1) * 2 + 1]);
        }
    }

    // ---- epilogue: out = as_m * (ws_n * acc + corr[n][m]) + bias ----
    #pragma unroll
    for (int mb = 0; mb < 4; mb++) {
        int m0 = bm + wm * 64 + mb * 16 + (lane >> 2);
        float as0 = g_ascale[m0];
        float as1 = g_ascale[m0 + 8];
        #pragma unroll
        for (int f = 0; f < 4; f++) {
            int gn = bn + wn * 32 + f * 8 + (lane & 3) * 2;
            float ws0 = g_wscale[gn], ws1 = g_wscale[gn + 1];
            float b0 = bias[gn], b1 = bias[gn + 1];
            const float* c0 = g_corr + (size_t)gn * MTOK;
            const float* c1 = c0 + MTOK;
            float2 o0 = make_float2(
                as0 * (ws0 * (float)acc[mb][f][0] + c0[m0]) + b0,
                as0 * (ws1 * (float)acc[mb][f][1] + c1[m0]) + b1);
            float2 o1 = make_float2(
                as1 * (ws0 * (float)acc[mb][f][2] + c0[m0 + 8]) + b0,
                as1 * (ws1 * (float)acc[mb][f][3] + c1[m0 + 8]) + b1);
            *(float2*)(C + (size_t)m0 * OUTN + gn)       = o0;
            *(float2*)(C + (size_t)(m0 + 8) * OUTN + gn) = o1;
        }
    }
}

// ---------------- launch ----------------
extern "C" void kernel_launch(void* const* d_in, const int* in_sizes, int n_in,
                              void* d_out, int out_size)
{
    const float* hs   = (const float*)d_in[0];  // (2,2048,4096)
    const float* w    = (const float*)d_in[1];  // (11008,4096)
    const float* bias = (const float*)d_in[2];  // (11008)
    const float* tl   = (const float*)d_in[3];  // (64,64)
    const float* tr   = (const float*)d_in[4];  // (64,64)
    const float* cmax = (const float*)d_in[5];  // (11008,1)
    const float* cmin = (const float*)d_in[6];  // (11008,1)
    float* out = (float*)d_out;

    static bool attr_set = false;
    if (!attr_set) {
        cudaFuncSetAttribute(k_gemm_i8, cudaFuncAttributeMaxDynamicSharedMemorySize, GSMEM);
        attr_set = true;
    }

    k_front<<<OUTN + MTOK, 256>>>(w, tl, tr, cmax, cmin, hs);   // launch 0
    k_mid<<<1024 + 4096, 256>>>();                              // launch 1
    k_wfinal2<<<OUTN, 256>>>();                                 // launch 2
    dim3 g(OUTN / 128, MTOK / 128);
    k_gemm_i8<<<g, 256, GSMEM>>>(bias, out);                    // launch 3
}

// round 9
// speedup vs baseline: 1.6184x; 1.6099x over previous
#include <cuda_runtime.h>
#include <cuda_bf16.h>
#include <math.h>

#define OUTN 11008
#define INN  4096
#define MTOK 4096            // 2 * 2048 tokens
#define NTOT 45088768        // OUTN * INN
#define SPADU 40             // smem row stride in b16 units (64B data + 16B pad)

// GEMM pipeline config (bf16, BK=32 elems = 64B rows)
#define TILEB 10240          // bytes per array per stage (128 rows * 80B)
#define STGB  (2 * TILEB)    // A + B per stage
#define NSTG  4
#define GSMEM (NSTG * STGB)  // 81920
#define NTILES 2752          // 86 n-tiles * 32 m-tiles
#define PGRID  296           // persistent: 2 CTAs/SM * 148

// ---------------- scratch (static device globals; no allocation) ----------------
__device__ float          g_wt[NTOT];          // transformed/clipped weights (fp32)
__device__ __nv_bfloat16  g_wqb[NTOT];         // int4-valued weights as bf16 (exact)
__device__ __nv_bfloat16  g_xab[MTOK * INN];   // int8-valued activations as bf16 (exact)
__device__ signed char    g_xq8[MTOK * INN];   // int8 activations (for corr path)
__device__ signed char    g_xq8T[INN * MTOK];  // transposed activations [k][m]
__device__ float          g_corr[NTOT];        // outlier correction [n][m]
__device__ float          g_wscale[OUTN];
__device__ float          g_ascale[MTOK];
__device__ float          g_rowabs[OUTN];
__device__ double         g_psum[OUTN];
__device__ double         g_psumsq[OUTN];
__device__ int            g_icnt;              // global outlier count (int atomic)
__device__ float          g_stats[4];          // [0]=mean, [1]=T=3*std

// ================ K0: transform (blocks 0..11007) + actq (blocks 11008..15103) ================
__global__ __launch_bounds__(256) void k_front(
    const float* __restrict__ W, const float* __restrict__ L,
    const float* __restrict__ R, const float* __restrict__ cmax,
    const float* __restrict__ cmin, const float* __restrict__ X)
{
    __shared__ double sAd[2048];   // 16KB, aliased as float sA[4096]
    __shared__ float  sL[4096];
    __shared__ float  sR[4096];
    float* sA = (float*)sAd;

    const int tid = threadIdx.x;

    if (blockIdx.x >= OUTN) {
        // ---- activation fake-quant for token t ----
        const int t = blockIdx.x - OUTN;
        if (t == 0 && tid == 0) g_icnt = 0;
        float* red = sL;
        const float* x = X + (size_t)t * INN;
        float4 vals[4];
        float la = 0.f;
        #pragma unroll
        for (int i = 0; i < 4; i++) {
            vals[i] = *(const float4*)&x[(tid + i * 256) * 4];
            la = fmaxf(la, fmaxf(fmaxf(fabsf(vals[i].x), fabsf(vals[i].y)),
                                 fmaxf(fabsf(vals[i].z), fabsf(vals[i].w))));
        }
        red[tid] = la;
        __syncthreads();
        for (int s = 128; s > 0; s >>= 1) {
            if (tid < s) red[tid] = fmaxf(red[tid], red[tid + s]);
            __syncthreads();
        }
        const float scale = red[0] / 127.0f + 1e-8f;
        if (tid == 0) g_ascale[t] = scale;
        signed char*   out8 = g_xq8 + (size_t)t * INN;
        __nv_bfloat16* outb = g_xab + (size_t)t * INN;
        #pragma unroll
        for (int i = 0; i < 4; i++) {
            float4 v = vals[i];
            float q0 = fminf(fmaxf(rintf(v.x / scale), -127.f), 127.f);
            float q1 = fminf(fmaxf(rintf(v.y / scale), -127.f), 127.f);
            float q2 = fminf(fmaxf(rintf(v.z / scale), -127.f), 127.f);
            float q3 = fminf(fmaxf(rintf(v.w / scale), -127.f), 127.f);
            union { int w; signed char b[4]; } p;
            p.b[0] = (signed char)q0; p.b[1] = (signed char)q1;
            p.b[2] = (signed char)q2; p.b[3] = (signed char)q3;
            *(int*)&out8[(tid + i * 256) * 4] = p.w;
            __nv_bfloat16 qb[4];
            qb[0] = __float2bfloat16_rn(q0); qb[1] = __float2bfloat16_rn(q1);
            qb[2] = __float2bfloat16_rn(q2); qb[3] = __float2bfloat16_rn(q3);
            *(uint2*)&outb[(tid + i * 256) * 4] = *(uint2*)qb;
        }
        return;
    }

    // ---- kronecker transform + clip + row stats for row o ----
    const int o = blockIdx.x;
    const int u = tid >> 4;
    const int v = tid & 15;

    const float* Wo = W + (size_t)o * INN;
    for (int i = tid; i < 4096; i += 256) { sA[i] = Wo[i]; sL[i] = L[i]; sR[i] = R[i]; }
    __syncthreads();

    float acc[4][4];
    #pragma unroll
    for (int j = 0; j < 4; j++)
        #pragma unroll
        for (int l = 0; l < 4; l++) acc[j][l] = 0.f;

    for (int b = 0; b < 64; b++) {
        float4 rr = *(const float4*)&sR[(b << 6) + (v << 2)];
        float  wr[4];
        #pragma unroll
        for (int j = 0; j < 4; j++) wr[j] = sA[(((u << 2) + j) << 6) + b];
        #pragma unroll
        for (int j = 0; j < 4; j++) {
            acc[j][0] = fmaf(wr[j], rr.x, acc[j][0]);
            acc[j][1] = fmaf(wr[j], rr.y, acc[j][1]);
            acc[j][2] = fmaf(wr[j], rr.z, acc[j][2]);
            acc[j][3] = fmaf(wr[j], rr.w, acc[j][3]);
        }
    }
    __syncthreads();
    #pragma unroll
    for (int j = 0; j < 4; j++)
        *(float4*)&sA[(((u << 2) + j) << 6) + (v << 2)] =
            make_float4(acc[j][0], acc[j][1], acc[j][2], acc[j][3]);
    __syncthreads();

    float vv[4][4];
    #pragma unroll
    for (int j = 0; j < 4; j++)
        #pragma unroll
        for (int l = 0; l < 4; l++) vv[j][l] = 0.f;

    for (int a = 0; a < 64; a++) {
        float4 td = *(const float4*)&sA[(a << 6) + (v << 2)];
        float4 lc = *(const float4*)&sL[(a << 6) + (u << 2)];
        float lcr[4] = {lc.x, lc.y, lc.z, lc.w};
        #pragma unroll
        for (int j = 0; j < 4; j++) {
            vv[j][0] = fmaf(lcr[j], td.x, vv[j][0]);
            vv[j][1] = fmaf(lcr[j], td.y, vv[j][1]);
            vv[j][2] = fmaf(lcr[j], td.z, vv[j][2]);
            vv[j][3] = fmaf(lcr[j], td.w, vv[j][3]);
        }
    }

    float lmin = 3.4e38f, lmax = -3.4e38f;
    #pragma unroll
    for (int j = 0; j < 4; j++)
        #pragma unroll
        for (int l = 0; l < 4; l++) { lmin = fminf(lmin, vv[j][l]); lmax = fmaxf(lmax, vv[j][l]); }

    __syncthreads();
    sR[tid] = lmin; sR[256 + tid] = lmax;
    __syncthreads();
    for (int s = 128; s > 0; s >>= 1) {
        if (tid < s) {
            sR[tid]       = fminf(sR[tid], sR[tid + s]);
            sR[256 + tid] = fmaxf(sR[256 + tid], sR[256 + tid + s]);
        }
        __syncthreads();
    }
    const float rmin = sR[0], rmax = sR[256];
    const float lo = rmin * (1.f / (1.f + expf(-cmin[o])));
    const float hi = rmax * (1.f / (1.f + expf(-cmax[o])));

    float la = 0.f; double ls = 0.0, lss = 0.0;
    #pragma unroll
    for (int j = 0; j < 4; j++)
        #pragma unroll
        for (int l = 0; l < 4; l++) {
            float w = fminf(fmaxf(vv[j][l], lo), hi);
            vv[j][l] = w;
            la = fmaxf(la, fabsf(w));
            ls += (double)w;
            lss += (double)w * (double)w;
        }

    __syncthreads();
    sAd[tid] = ls; sAd[256 + tid] = lss; sR[tid] = la;
    __syncthreads();
    for (int s = 128; s > 0; s >>= 1) {
        if (tid < s) {
            sAd[tid]       += sAd[tid + s];
            sAd[256 + tid] += sAd[256 + tid + s];
            sR[tid] = fmaxf(sR[tid], sR[tid + s]);
        }
        __syncthreads();
    }
    if (tid == 0) { g_psum[o] = sAd[0]; g_psumsq[o] = sAd[256]; g_rowabs[o] = sR[0]; }

    float* outp = g_wt + (size_t)o * INN;
    #pragma unroll
    for (int j = 0; j < 4; j++)
        *(float4*)&outp[(((u << 2) + j) << 6) + (v << 2)] =
            make_float4(vv[j][0], vv[j][1], vv[j][2], vv[j][3]);
}

// ================ K1: stats+count (blocks 0..1023) + transpose xT (blocks 1024..5119) ================
__global__ __launch_bounds__(256) void k_mid()
{
    __shared__ double ds[512];
    __shared__ int    sc[256];
    __shared__ signed char ts[64 * 65];

    const int tid = threadIdx.x;

    if (blockIdx.x >= 1024) {
        int b2 = blockIdx.x - 1024;
        int k0 = (b2 & 63) * 64, m0 = (b2 >> 6) * 64;
        int r  = tid >> 2;
        int c4 = (tid & 3) * 16;
        union { int4 v; signed char b[16]; } u;
        u.v = *(const int4*)(g_xq8 + (size_t)(m0 + r) * INN + k0 + c4);
        #pragma unroll
        for (int i = 0; i < 16; i++) ts[r * 65 + c4 + i] = u.b[i];
        __syncthreads();
        #pragma unroll
        for (int i = 0; i < 16; i++) u.b[i] = ts[(c4 + i) * 65 + r];
        *(int4*)(g_xq8T + (size_t)(k0 + r) * MTOK + m0 + c4) = u.v;
        return;
    }

    double s = 0.0, ss = 0.0;
    for (int i = tid; i < OUTN; i += 256) { s += g_psum[i]; ss += g_psumsq[i]; }
    ds[tid] = s; ds[256 + tid] = ss;
    __syncthreads();
    for (int st = 128; st > 0; st >>= 1) {
        if (tid < st) { ds[tid] += ds[tid + st]; ds[256 + tid] += ds[256 + tid + st]; }
        __syncthreads();
    }
    double mean_d = ds[0] / (double)NTOT;
    double var    = ds[256] / (double)NTOT - mean_d * mean_d;
    if (var < 0.0) var = 0.0;
    const float mean = (float)mean_d;
    const float T    = (float)(3.0 * sqrt(var));
    if (blockIdx.x == 0 && tid == 0) { g_stats[0] = mean; g_stats[1] = T; }

    int cnt = 0;
    size_t stride = (size_t)1024 * 256 * 4;
    for (size_t i = ((size_t)blockIdx.x * 256 + tid) * 4; i < (size_t)NTOT; i += stride) {
        float4 w4 = *(const float4*)(g_wt + i);
        cnt += (fabsf(w4.x - mean) > T) + (fabsf(w4.y - mean) > T)
             + (fabsf(w4.z - mean) > T) + (fabsf(w4.w - mean) > T);
    }
    sc[tid] = cnt;
    __syncthreads();
    for (int st = 128; st > 0; st >>= 1) {
        if (tid < st) sc[tid] += sc[tid + st];
        __syncthreads();
    }
    if (tid == 0) atomicAdd(&g_icnt, sc[0]);
}

// ================ K2: per-row quantize (-> bf16 q) + sparse list (smem) + corr row ================
__global__ __launch_bounds__(256) void k_wfinal2()
{
    __shared__ int            scnt[256];
    __shared__ unsigned short sk[4096];
    __shared__ float          sdl[4096];

    const int o   = blockIdx.x;
    const int tid = threadIdx.x;
    const float a1 = 0.01f;
    const float T = g_stats[1];
    const float frac = (float)g_icnt / (float)NTOT;
    const bool like = (frac > 1e-4f && frac < 0.05f);

    float ra = g_rowabs[o];
    float m = (like && ra > T) ? (T + (ra - T) * a1) : ra;   // fold monotone in |w|
    float scale = m / 7.0f + 1e-8f;
    if (tid == 0) g_wscale[o] = scale;

    const float* wrow = g_wt + (size_t)o * INN;

    __nv_bfloat16 qb[16];
    float dl[16];
    unsigned tagmask = 0;
    int cnt = 0;

    #pragma unroll
    for (int g = 0; g < 4; g++) {
        float4 w4 = *(const float4*)(wrow + tid * 16 + g * 4);
        float wv[4] = {w4.x, w4.y, w4.z, w4.w};
        #pragma unroll
        for (int e = 0; e < 4; e++) {
            int idx = g * 4 + e;
            float w = wv[e];
            bool tg = like && (fabsf(w) > T);
            float win = tg ? copysignf(T + (fabsf(w) - T) * a1, w) : w;
            float q = fminf(fmaxf(rintf(win / scale), -7.f), 7.f);
            float wq = q * scale;
            float wfin = tg ? copysignf(T + (fabsf(wq) - T) / a1, w) : wq;
            qb[idx] = __float2bfloat16_rn(q);   // exact small integer
            dl[idx] = wfin - wq;                // zero for untagged
            if (tg) { tagmask |= (1u << idx); cnt++; }
        }
    }
    {
        __nv_bfloat16* wb = g_wqb + (size_t)o * INN + tid * 16;
        *(uint4*)wb       = *(uint4*)&qb[0];
        *(uint4*)(wb + 8) = *(uint4*)&qb[8];
    }

    scnt[tid] = cnt;
    __syncthreads();
    for (int s = 1; s < 256; s <<= 1) {
        int v = 0;
        if (tid >= s) v = scnt[tid - s];
        __syncthreads();
        if (tid >= s) scnt[tid] += v;
        __syncthreads();
    }
    int off = scnt[tid] - cnt;
    __syncthreads();
    const int total = scnt[255];

    #pragma unroll
    for (int idx = 0; idx < 16; idx++) {
        if (tagmask & (1u << idx)) {
            sk[off]  = (unsigned short)(tid * 16 + idx);
            sdl[off] = dl[idx];
            off++;
        }
    }
    __syncthreads();

    float cv[16];
    #pragma unroll
    for (int i = 0; i < 16; i++) cv[i] = 0.f;
    for (int t = 0; t < total; t++) {
        const signed char* col = g_xq8T + (size_t)sk[t] * MTOK;
        float d = sdl[t];
        #pragma unroll
        for (int i = 0; i < 16; i++)
            cv[i] += (float)col[tid + i * 256] * d;
    }
    float* outc = g_corr + (size_t)o * MTOK;
    #pragma unroll
    for (int i = 0; i < 16; i++) outc[tid + i * 256] = cv[i];
}

// ================ K3: persistent bf16 HMMA GEMM (exact integer accumulation) ================
__device__ __forceinline__ void cpasync16(unsigned saddr, const void* g)
{
    asm volatile("cp.async.ca.shared.global [%0], [%1], 16;\n" :: "r"(saddr), "l"(g));
}
__device__ __forceinline__ void ldsm4(unsigned* r, unsigned saddr)
{
    asm volatile("ldmatrix.sync.aligned.m8n8.x4.shared.b16 {%0,%1,%2,%3}, [%4];"
                 : "=r"(r[0]), "=r"(r[1]), "=r"(r[2]), "=r"(r[3]) : "r"(saddr));
}
__device__ __forceinline__ void mma16816(float* d, const unsigned* a, unsigned b0, unsigned b1)
{
    asm volatile("mma.sync.aligned.m16n8k16.row.col.f32.bf16.bf16.f32 "
                 "{%0,%1,%2,%3}, {%4,%5,%6,%7}, {%8,%9}, {%0,%1,%2,%3};"
                 : "+f"(d[0]), "+f"(d[1]), "+f"(d[2]), "+f"(d[3])
                 : "r"(a[0]), "r"(a[1]), "r"(a[2]), "r"(a[3]), "r"(b0), "r"(b1));
}

__global__ __launch_bounds__(256, 2) void k_gemm_bf(const float* __restrict__ bias,
                                                    float* __restrict__ C)
{
    extern __shared__ char dsm[];

    const int tid  = threadIdx.x;
    const int lane = tid & 31;
    const int wid  = tid >> 5;
    const int wm   = wid & 1;       // 2 warps in M
    const int wn   = wid >> 1;      // 4 warps in N

    const int lrow  = tid >> 2;          // 0..63
    const int lcolu = (tid & 3) * 8;     // element/b16 col 0,8,16,24

    const int KITERS = INN / 32;   // 128

    for (int t = blockIdx.x; t < NTILES; t += gridDim.x) {
        const int bm = (t & 31) * 128;   // m inner: A tiles cycle within L2
        const int bn = (t >> 5) * 128;

        const __nv_bfloat16* Abase = g_xab + (size_t)bm * INN;
        const __nv_bfloat16* Bbase = g_wqb + (size_t)bn * INN;

        float acc[4][4][4];
        #pragma unroll
        for (int i = 0; i < 4; i++)
            #pragma unroll
            for (int j = 0; j < 4; j++)
                #pragma unroll
                for (int l = 0; l < 4; l++) acc[i][j][l] = 0.f;

        auto fill = [&](int it) {
            int s = it & 3;
            int k = it * 32;
            unsigned sA = (unsigned)__cvta_generic_to_shared(dsm + s * STGB);
            unsigned sB = sA + TILEB;
            #pragma unroll
            for (int i = 0; i < 2; i++) {
                int row = lrow + i * 64;
                cpasync16(sA + (row * SPADU + lcolu) * 2,
                          Abase + (size_t)row * INN + k + lcolu);
                cpasync16(sB + (row * SPADU + lcolu) * 2,
                          Bbase + (size_t)row * INN + k + lcolu);
            }
            asm volatile("cp.async.commit_group;\n");
        };

        fill(0); fill(1); fill(2);

        for (int it = 0; it < KITERS; ++it) {
            if (it < KITERS - 2)       asm volatile("cp.async.wait_group 2;\n");
            else if (it == KITERS - 2) asm volatile("cp.async.wait_group 1;\n");
            else                       asm volatile("cp.async.wait_group 0;\n");
            __syncthreads();

            if (it + 3 < KITERS) fill(it + 3);

            unsigned tb = (unsigned)__cvta_generic_to_shared(dsm + (it & 3) * STGB);
            unsigned tA = tb, tB = tb + TILEB;

            #pragma unroll
            for (int ks = 0; ks < 2; ks++) {
                unsigned afr[4][4], bfr[2][4];
                int arow = wm * 64 + (lane & 15);
                int acol = ks * 16 + (lane >> 4) * 8;
                #pragma unroll
                for (int mb = 0; mb < 4; mb++)
                    ldsm4(afr[mb], tA + ((arow + mb * 16) * SPADU + acol) * 2);
                int brow = wn * 32 + (lane & 7) + ((lane >> 4) & 1) * 8;
                int bcol = ks * 16 + ((lane >> 3) & 1) * 8;
                #pragma unroll
                for (int nb = 0; nb < 2; nb++)
                    ldsm4(bfr[nb], tB + ((brow + nb * 16) * SPADU + bcol) * 2);
                #pragma unroll
                for (int mb = 0; mb < 4; mb++)
                    #pragma unroll
                    for (int f = 0; f < 4; f++)
                        mma16816(acc[mb][f], afr[mb],
                                 bfr[f >> 1][(f & 1) * 2], bfr[f >> 1][(f & 1) * 2 + 1]);
            }
        }

        // ---- epilogue: out = as_m * (ws_n * acc + corr[n][m]) + bias ----
        #pragma unroll
        for (int mb = 0; mb < 4; mb++) {
            int m0 = bm + wm * 64 + mb * 16 + (lane >> 2);
            float as0 = g_ascale[m0];
            float as1 = g_ascale[m0 + 8];
            #pragma unroll
            for (int f = 0; f < 4; f++) {
                int gn = bn + wn * 32 + f * 8 + (lane & 3) * 2;
                float ws0 = g_wscale[gn], ws1 = g_wscale[gn + 1];
                float b0 = bias[gn], b1 = bias[gn + 1];
                const float* c0 = g_corr + (size_t)gn * MTOK;
                const float* c1 = c0 + MTOK;
                float2 o0 = make_float2(
                    as0 * (ws0 * acc[mb][f][0] + c0[m0]) + b0,
                    as0 * (ws1 * acc[mb][f][1] + c1[m0]) + b1);
                float2 o1 = make_float2(
                    as1 * (ws0 * acc[mb][f][2] + c0[m0 + 8]) + b0,
                    as1 * (ws1 * acc[mb][f][3] + c1[m0 + 8]) + b1);
                *(float2*)(C + (size_t)m0 * OUTN + gn)       = o0;
                *(float2*)(C + (size_t)(m0 + 8) * OUTN + gn) = o1;
            }
        }
        __syncthreads();   // smem safe for next tile's fills
    }
}

// ---------------- launch ----------------
extern "C" void kernel_launch(void* const* d_in, const int* in_sizes, int n_in,
                              void* d_out, int out_size)
{
    const float* hs   = (const float*)d_in[0];  // (2,2048,4096)
    const float* w    = (const float*)d_in[1];  // (11008,4096)
    const float* bias = (const float*)d_in[2];  // (11008)
    const float* tl   = (const float*)d_in[3];  // (64,64)
    const float* tr   = (const float*)d_in[4];  // (64,64)
    const float* cmax = (const float*)d_in[5];  // (11008,1)
    const float* cmin = (const float*)d_in[6];  // (11008,1)
    float* out = (float*)d_out;

    static bool attr_set = false;
    if (!attr_set) {
        cudaFuncSetAttribute(k_gemm_bf, cudaFuncAttributeMaxDynamicSharedMemorySize, GSMEM);
        attr_set = true;
    }

    k_front<<<OUTN + MTOK, 256>>>(w, tl, tr, cmax, cmin, hs);   // launch 0
    k_mid<<<1024 + 4096, 256>>>();                              // launch 1
    k_wfinal2<<<OUTN, 256>>>();                                 // launch 2
    k_gemm_bf<<<PGRID, 256, GSMEM>>>(bias, out);                // launch 3
}

// round 10
// speedup vs baseline: 1.8229x; 1.1264x over previous
#include <cuda_runtime.h>
#include <cuda_bf16.h>
#include <math.h>

#define OUTN 11008
#define INN  4096
#define MTOK 4096            // 2 * 2048 tokens
#define NTOT 45088768        // OUTN * INN
#define SPADU 40             // smem row stride in b16 units (64B data + 16B pad)

// GEMM pipeline config (bf16, BK=32 elems = 64B rows)
#define TILEB 10240          // bytes per array per stage (128 rows * 80B)
#define STGB  (2 * TILEB)    // A + B per stage
#define NSTG  4
#define GSMEM (NSTG * STGB)  // 81920
#define NTILES 2752          // 86 n-tiles * 32 m-tiles
#define PGRID  296           // persistent: 2 CTAs/SM * 148

// ---------------- scratch (static device globals; no allocation) ----------------
__device__ float          g_wt[NTOT];          // transformed/clipped weights (fp32)
__device__ __nv_bfloat16  g_wqb[NTOT];         // int4-valued weights as bf16 (exact)
__device__ __nv_bfloat16  g_xab[MTOK * INN];   // int8-valued activations as bf16 (exact)
__device__ signed char    g_xq8[MTOK * INN];   // int8 activations (for corr path)
__device__ signed char    g_xq8T[INN * MTOK];  // transposed activations [k][m]
__device__ float          g_corr[NTOT];        // outlier correction [n][m]
__device__ float          g_wscale[OUTN];
__device__ float          g_ascale[MTOK];
__device__ float          g_rowabs[OUTN];
__device__ double         g_psum[OUTN];
__device__ double         g_psumsq[OUTN];
__device__ int            g_icnt;              // global outlier count (int atomic)
__device__ float          g_stats[4];          // [0]=mean, [1]=T=3*std

// ================ K0: transform (blocks 0..11007) + actq (blocks 11008..15103) ================
__global__ __launch_bounds__(256) void k_front(
    const float* __restrict__ W, const float* __restrict__ L,
    const float* __restrict__ R, const float* __restrict__ cmax,
    const float* __restrict__ cmin, const float* __restrict__ X)
{
    __shared__ double sAd[2048];   // 16KB, aliased as float sA[4096]
    __shared__ float  sL[4096];
    __shared__ float  sR[4096];
    float* sA = (float*)sAd;

    const int tid = threadIdx.x;

    if (blockIdx.x >= OUTN) {
        // ---- activation fake-quant for token t ----
        const int t = blockIdx.x - OUTN;
        if (t == 0 && tid == 0) g_icnt = 0;
        float* red = sL;
        const float* x = X + (size_t)t * INN;
        float4 vals[4];
        float la = 0.f;
        #pragma unroll
        for (int i = 0; i < 4; i++) {
            vals[i] = *(const float4*)&x[(tid + i * 256) * 4];
            la = fmaxf(la, fmaxf(fmaxf(fabsf(vals[i].x), fabsf(vals[i].y)),
                                 fmaxf(fabsf(vals[i].z), fabsf(vals[i].w))));
        }
        red[tid] = la;
        __syncthreads();
        for (int s = 128; s > 0; s >>= 1) {
            if (tid < s) red[tid] = fmaxf(red[tid], red[tid + s]);
            __syncthreads();
        }
        const float scale = red[0] / 127.0f + 1e-8f;
        if (tid == 0) g_ascale[t] = scale;
        signed char*   out8 = g_xq8 + (size_t)t * INN;
        __nv_bfloat16* outb = g_xab + (size_t)t * INN;
        #pragma unroll
        for (int i = 0; i < 4; i++) {
            float4 v = vals[i];
            float q0 = fminf(fmaxf(rintf(v.x / scale), -127.f), 127.f);
            float q1 = fminf(fmaxf(rintf(v.y / scale), -127.f), 127.f);
            float q2 = fminf(fmaxf(rintf(v.z / scale), -127.f), 127.f);
            float q3 = fminf(fmaxf(rintf(v.w / scale), -127.f), 127.f);
            union { int w; signed char b[4]; } p;
            p.b[0] = (signed char)q0; p.b[1] = (signed char)q1;
            p.b[2] = (signed char)q2; p.b[3] = (signed char)q3;
            *(int*)&out8[(tid + i * 256) * 4] = p.w;
            __nv_bfloat16 qb[4];
            qb[0] = __float2bfloat16_rn(q0); qb[1] = __float2bfloat16_rn(q1);
            qb[2] = __float2bfloat16_rn(q2); qb[3] = __float2bfloat16_rn(q3);
            *(uint2*)&outb[(tid + i * 256) * 4] = *(uint2*)qb;
        }
        return;
    }

    // ---- kronecker transform + clip + row stats for row o ----
    const int o = blockIdx.x;
    const int u = tid >> 4;
    const int v = tid & 15;

    const float* Wo = W + (size_t)o * INN;
    for (int i = tid; i < 4096; i += 256) { sA[i] = Wo[i]; sL[i] = L[i]; sR[i] = R[i]; }
    __syncthreads();

    float acc[4][4];
    #pragma unroll
    for (int j = 0; j < 4; j++)
        #pragma unroll
        for (int l = 0; l < 4; l++) acc[j][l] = 0.f;

    for (int b = 0; b < 64; b++) {
        float4 rr = *(const float4*)&sR[(b << 6) + (v << 2)];
        float  wr[4];
        #pragma unroll
        for (int j = 0; j < 4; j++) wr[j] = sA[(((u << 2) + j) << 6) + b];
        #pragma unroll
        for (int j = 0; j < 4; j++) {
            acc[j][0] = fmaf(wr[j], rr.x, acc[j][0]);
            acc[j][1] = fmaf(wr[j], rr.y, acc[j][1]);
            acc[j][2] = fmaf(wr[j], rr.z, acc[j][2]);
            acc[j][3] = fmaf(wr[j], rr.w, acc[j][3]);
        }
    }
    __syncthreads();
    #pragma unroll
    for (int j = 0; j < 4; j++)
        *(float4*)&sA[(((u << 2) + j) << 6) + (v << 2)] =
            make_float4(acc[j][0], acc[j][1], acc[j][2], acc[j][3]);
    __syncthreads();

    float vv[4][4];
    #pragma unroll
    for (int j = 0; j < 4; j++)
        #pragma unroll
        for (int l = 0; l < 4; l++) vv[j][l] = 0.f;

    for (int a = 0; a < 64; a++) {
        float4 td = *(const float4*)&sA[(a << 6) + (v << 2)];
        float4 lc = *(const float4*)&sL[(a << 6) + (u << 2)];
        float lcr[4] = {lc.x, lc.y, lc.z, lc.w};
        #pragma unroll
        for (int j = 0; j < 4; j++) {
            vv[j][0] = fmaf(lcr[j], td.x, vv[j][0]);
            vv[j][1] = fmaf(lcr[j], td.y, vv[j][1]);
            vv[j][2] = fmaf(lcr[j], td.z, vv[j][2]);
            vv[j][3] = fmaf(lcr[j], td.w, vv[j][3]);
        }
    }

    float lmin = 3.4e38f, lmax = -3.4e38f;
    #pragma unroll
    for (int j = 0; j < 4; j++)
        #pragma unroll
        for (int l = 0; l < 4; l++) { lmin = fminf(lmin, vv[j][l]); lmax = fmaxf(lmax, vv[j][l]); }

    __syncthreads();
    sR[tid] = lmin; sR[256 + tid] = lmax;
    __syncthreads();
    for (int s = 128; s > 0; s >>= 1) {
        if (tid < s) {
            sR[tid]       = fminf(sR[tid], sR[tid + s]);
            sR[256 + tid] = fmaxf(sR[256 + tid], sR[256 + tid + s]);
        }
        __syncthreads();
    }
    const float rmin = sR[0], rmax = sR[256];
    const float lo = rmin * (1.f / (1.f + expf(-cmin[o])));
    const float hi = rmax * (1.f / (1.f + expf(-cmax[o])));

    float la = 0.f; double ls = 0.0, lss = 0.0;
    #pragma unroll
    for (int j = 0; j < 4; j++)
        #pragma unroll
        for (int l = 0; l < 4; l++) {
            float w = fminf(fmaxf(vv[j][l], lo), hi);
            vv[j][l] = w;
            la = fmaxf(la, fabsf(w));
            ls += (double)w;
            lss += (double)w * (double)w;
        }

    __syncthreads();
    sAd[tid] = ls; sAd[256 + tid] = lss; sR[tid] = la;
    __syncthreads();
    for (int s = 128; s > 0; s >>= 1) {
        if (tid < s) {
            sAd[tid]       += sAd[tid + s];
            sAd[256 + tid] += sAd[256 + tid + s];
            sR[tid] = fmaxf(sR[tid], sR[tid + s]);
        }
        __syncthreads();
    }
    if (tid == 0) { g_psum[o] = sAd[0]; g_psumsq[o] = sAd[256]; g_rowabs[o] = sR[0]; }

    float* outp = g_wt + (size_t)o * INN;
    #pragma unroll
    for (int j = 0; j < 4; j++)
        *(float4*)&outp[(((u << 2) + j) << 6) + (v << 2)] =
            make_float4(vv[j][0], vv[j][1], vv[j][2], vv[j][3]);
}

// ================ K1: stats+count (blocks 0..1023) + transpose xT (blocks 1024..5119) ================
__global__ __launch_bounds__(256) void k_mid()
{
    __shared__ double ds[512];
    __shared__ int    sc[256];
    __shared__ signed char ts[64 * 65];

    const int tid = threadIdx.x;

    if (blockIdx.x >= 1024) {
        int b2 = blockIdx.x - 1024;
        int k0 = (b2 & 63) * 64, m0 = (b2 >> 6) * 64;
        int r  = tid >> 2;
        int c4 = (tid & 3) * 16;
        union { int4 v; signed char b[16]; } u;
        u.v = *(const int4*)(g_xq8 + (size_t)(m0 + r) * INN + k0 + c4);
        #pragma unroll
        for (int i = 0; i < 16; i++) ts[r * 65 + c4 + i] = u.b[i];
        __syncthreads();
        #pragma unroll
        for (int i = 0; i < 16; i++) u.b[i] = ts[(c4 + i) * 65 + r];
        *(int4*)(g_xq8T + (size_t)(k0 + r) * MTOK + m0 + c4) = u.v;
        return;
    }

    double s = 0.0, ss = 0.0;
    for (int i = tid; i < OUTN; i += 256) { s += g_psum[i]; ss += g_psumsq[i]; }
    ds[tid] = s; ds[256 + tid] = ss;
    __syncthreads();
    for (int st = 128; st > 0; st >>= 1) {
        if (tid < st) { ds[tid] += ds[tid + st]; ds[256 + tid] += ds[256 + tid + st]; }
        __syncthreads();
    }
    double mean_d = ds[0] / (double)NTOT;
    double var    = ds[256] / (double)NTOT - mean_d * mean_d;
    if (var < 0.0) var = 0.0;
    const float mean = (float)mean_d;
    const float T    = (float)(3.0 * sqrt(var));
    if (blockIdx.x == 0 && tid == 0) { g_stats[0] = mean; g_stats[1] = T; }

    int cnt = 0;
    size_t stride = (size_t)1024 * 256 * 4;
    for (size_t i = ((size_t)blockIdx.x * 256 + tid) * 4; i < (size_t)NTOT; i += stride) {
        float4 w4 = *(const float4*)(g_wt + i);
        cnt += (fabsf(w4.x - mean) > T) + (fabsf(w4.y - mean) > T)
             + (fabsf(w4.z - mean) > T) + (fabsf(w4.w - mean) > T);
    }
    sc[tid] = cnt;
    __syncthreads();
    for (int st = 128; st > 0; st >>= 1) {
        if (tid < st) sc[tid] += sc[tid + st];
        __syncthreads();
    }
    if (tid == 0) atomicAdd(&g_icnt, sc[0]);
}

// ================ K2: per-row quantize (-> bf16 q) + sparse list (smem) + corr row ================
__global__ __launch_bounds__(256) void k_wfinal2()
{
    __shared__ int            scnt[256];
    __shared__ unsigned short sk[4096];
    __shared__ float          sdl[4096];

    const int o   = blockIdx.x;
    const int tid = threadIdx.x;
    const float a1 = 0.01f;
    const float T = g_stats[1];
    const float frac = (float)g_icnt / (float)NTOT;
    const bool like = (frac > 1e-4f && frac < 0.05f);

    float ra = g_rowabs[o];
    float m = (like && ra > T) ? (T + (ra - T) * a1) : ra;   // fold monotone in |w|
    float scale = m / 7.0f + 1e-8f;
    if (tid == 0) g_wscale[o] = scale;

    const float* wrow = g_wt + (size_t)o * INN;

    __nv_bfloat16 qb[16];
    float dl[16];
    unsigned tagmask = 0;
    int cnt = 0;

    #pragma unroll
    for (int g = 0; g < 4; g++) {
        float4 w4 = *(const float4*)(wrow + tid * 16 + g * 4);
        float wv[4] = {w4.x, w4.y, w4.z, w4.w};
        #pragma unroll
        for (int e = 0; e < 4; e++) {
            int idx = g * 4 + e;
            float w = wv[e];
            bool tg = like && (fabsf(w) > T);
            float win = tg ? copysignf(T + (fabsf(w) - T) * a1, w) : w;
            float q = fminf(fmaxf(rintf(win / scale), -7.f), 7.f);
            float wq = q * scale;
            float wfin = tg ? copysignf(T + (fabsf(wq) - T) / a1, w) : wq;
            qb[idx] = __float2bfloat16_rn(q);   // exact small integer
            dl[idx] = wfin - wq;                // zero for untagged
            if (tg) { tagmask |= (1u << idx); cnt++; }
        }
    }
    {
        __nv_bfloat16* wb = g_wqb + (size_t)o * INN + tid * 16;
        *(uint4*)wb       = *(uint4*)&qb[0];
        *(uint4*)(wb + 8) = *(uint4*)&qb[8];
    }

    scnt[tid] = cnt;
    __syncthreads();
    for (int s = 1; s < 256; s <<= 1) {
        int v = 0;
        if (tid >= s) v = scnt[tid - s];
        __syncthreads();
        if (tid >= s) scnt[tid] += v;
        __syncthreads();
    }
    int off = scnt[tid] - cnt;
    __syncthreads();
    const int total = scnt[255];

    #pragma unroll
    for (int idx = 0; idx < 16; idx++) {
        if (tagmask & (1u << idx)) {
            sk[off]  = (unsigned short)(tid * 16 + idx);
            sdl[off] = dl[idx];
            off++;
        }
    }
    __syncthreads();

    float cv[16];
    #pragma unroll
    for (int i = 0; i < 16; i++) cv[i] = 0.f;
    for (int t = 0; t < total; t++) {
        const signed char* col = g_xq8T + (size_t)sk[t] * MTOK;
        float d = sdl[t];
        #pragma unroll
        for (int i = 0; i < 16; i++)
            cv[i] += (float)col[tid + i * 256] * d;
    }
    float* outc = g_corr + (size_t)o * MTOK;
    #pragma unroll
    for (int i = 0; i < 16; i++) outc[tid + i * 256] = cv[i];
}

// ================ K3: persistent bf16 HMMA GEMM, 64x64 warp tiles ================
__device__ __forceinline__ void cpasync16(unsigned saddr, const void* g)
{
    asm volatile("cp.async.ca.shared.global [%0], [%1], 16;\n" :: "r"(saddr), "l"(g));
}
__device__ __forceinline__ void ldsm4(unsigned* r, unsigned saddr)
{
    asm volatile("ldmatrix.sync.aligned.m8n8.x4.shared.b16 {%0,%1,%2,%3}, [%4];"
                 : "=r"(r[0]), "=r"(r[1]), "=r"(r[2]), "=r"(r[3]) : "r"(saddr));
}
__device__ __forceinline__ void mma16816(float* d, const unsigned* a, unsigned b0, unsigned b1)
{
    asm volatile("mma.sync.aligned.m16n8k16.row.col.f32.bf16.bf16.f32 "
                 "{%0,%1,%2,%3}, {%4,%5,%6,%7}, {%8,%9}, {%0,%1,%2,%3};"
                 : "+f"(d[0]), "+f"(d[1]), "+f"(d[2]), "+f"(d[3])
                 : "r"(a[0]), "r"(a[1]), "r"(a[2]), "r"(a[3]), "r"(b0), "r"(b1));
}

__global__ __launch_bounds__(128, 2) void k_gemm_bf(const float* __restrict__ bias,
                                                    float* __restrict__ C)
{
    extern __shared__ char dsm[];

    const int tid  = threadIdx.x;
    const int lane = tid & 31;
    const int wid  = tid >> 5;      // 0..3
    const int wm   = wid & 1;       // 2 warps in M
    const int wn   = wid >> 1;      // 2 warps in N

    const int lrow  = tid >> 2;          // 0..31
    const int lcolu = (tid & 3) * 8;     // element col 0,8,16,24

    const int KITERS = INN / 32;   // 128

    for (int t = blockIdx.x; t < NTILES; t += gridDim.x) {
        const int bm = (t & 31) * 128;   // m inner: A tiles cycle within L2
        const int bn = (t >> 5) * 128;

        const __nv_bfloat16* Abase = g_xab + (size_t)bm * INN;
        const __nv_bfloat16* Bbase = g_wqb + (size_t)bn * INN;

        float acc[4][8][4];
        #pragma unroll
        for (int i = 0; i < 4; i++)
            #pragma unroll
            for (int j = 0; j < 8; j++)
                #pragma unroll
                for (int l = 0; l < 4; l++) acc[i][j][l] = 0.f;

        auto fill = [&](int it) {
            int s = it & 3;
            int k = it * 32;
            unsigned sA = (unsigned)__cvta_generic_to_shared(dsm + s * STGB);
            unsigned sB = sA + TILEB;
            #pragma unroll
            for (int i = 0; i < 4; i++) {
                int row = lrow + i * 32;
                cpasync16(sA + (row * SPADU + lcolu) * 2,
                          Abase + (size_t)row * INN + k + lcolu);
                cpasync16(sB + (row * SPADU + lcolu) * 2,
                          Bbase + (size_t)row * INN + k + lcolu);
            }
            asm volatile("cp.async.commit_group;\n");
        };

        fill(0); fill(1); fill(2);

        for (int it = 0; it < KITERS; ++it) {
            if (it < KITERS - 2)       asm volatile("cp.async.wait_group 2;\n");
            else if (it == KITERS - 2) asm volatile("cp.async.wait_group 1;\n");
            else                       asm volatile("cp.async.wait_group 0;\n");
            __syncthreads();

            if (it + 3 < KITERS) fill(it + 3);

            unsigned tb = (unsigned)__cvta_generic_to_shared(dsm + (it & 3) * STGB);
            unsigned tA = tb, tB = tb + TILEB;

            #pragma unroll
            for (int ks = 0; ks < 2; ks++) {
                unsigned afr[4][4], bfr[4][4];
                int arow = wm * 64 + (lane & 15);
                int acol = ks * 16 + (lane >> 4) * 8;
                #pragma unroll
                for (int mb = 0; mb < 4; mb++)
                    ldsm4(afr[mb], tA + ((arow + mb * 16) * SPADU + acol) * 2);
                int brow = wn * 64 + (lane & 7) + ((lane >> 4) & 1) * 8;
                int bcol = ks * 16 + ((lane >> 3) & 1) * 8;
                #pragma unroll
                for (int nb = 0; nb < 4; nb++)
                    ldsm4(bfr[nb], tB + ((brow + nb * 16) * SPADU + bcol) * 2);
                #pragma unroll
                for (int mb = 0; mb < 4; mb++)
                    #pragma unroll
                    for (int f = 0; f < 8; f++)
                        mma16816(acc[mb][f], afr[mb],
                                 bfr[f >> 1][(f & 1) * 2], bfr[f >> 1][(f & 1) * 2 + 1]);
            }
        }

        // ---- epilogue: out = as_m * (ws_n * acc + corr[n][m]) + bias ----
        #pragma unroll
        for (int mb = 0; mb < 4; mb++) {
            int m0 = bm + wm * 64 + mb * 16 + (lane >> 2);
            float as0 = g_ascale[m0];
            float as1 = g_ascale[m0 + 8];
            #pragma unroll
            for (int f = 0; f < 8; f++) {
                int gn = bn + wn * 64 + f * 8 + (lane & 3) * 2;
                float ws0 = g_wscale[gn], ws1 = g_wscale[gn + 1];
                float b0 = bias[gn], b1 = bias[gn + 1];
                const float* c0 = g_corr + (size_t)gn * MTOK;
                const float* c1 = c0 + MTOK;
                float2 o0 = make_float2(
                    as0 * (ws0 * acc[mb][f][0] + c0[m0]) + b0,
                    as0 * (ws1 * acc[mb][f][1] + c1[m0]) + b1);
                float2 o1 = make_float2(
                    as1 * (ws0 * acc[mb][f][2] + c0[m0 + 8]) + b0,
                    as1 * (ws1 * acc[mb][f][3] + c1[m0 + 8]) + b1);
                *(float2*)(C + (size_t)m0 * OUTN + gn)       = o0;
                *(float2*)(C + (size_t)(m0 + 8) * OUTN + gn) = o1;
            }
        }
        __syncthreads();   // smem safe for next tile's fills
    }
}

// ---------------- launch ----------------
extern "C" void kernel_launch(void* const* d_in, const int* in_sizes, int n_in,
                              void* d_out, int out_size)
{
    const float* hs   = (const float*)d_in[0];  // (2,2048,4096)
    const float* w    = (const float*)d_in[1];  // (11008,4096)
    const float* bias = (const float*)d_in[2];  // (11008)
    const float* tl   = (const float*)d_in[3];  // (64,64)
    const float* tr   = (const float*)d_in[4];  // (64,64)
    const float* cmax = (const float*)d_in[5];  // (11008,1)
    const float* cmin = (const float*)d_in[6];  // (11008,1)
    float* out = (float*)d_out;

    static bool attr_set = false;
    if (!attr_set) {
        cudaFuncSetAttribute(k_gemm_bf, cudaFuncAttributeMaxDynamicSharedMemorySize, GSMEM);
        attr_set = true;
    }

    k_front<<<OUTN + MTOK, 256>>>(w, tl, tr, cmax, cmin, hs);   // launch 0
    k_mid<<<1024 + 4096, 256>>>();                              // launch 1
    k_wfinal2<<<OUTN, 256>>>();                                 // launch 2
    k_gemm_bf<<<PGRID, 128, GSMEM>>>(bias, out);                // launch 3
}

// round 11
// speedup vs baseline: 1.8329x; 1.0055x over previous
#include <cuda_runtime.h>
#include <cuda_bf16.h>
#include <math.h>

#define OUTN 11008
#define INN  4096
#define MTOK 4096            // 2 * 2048 tokens
#define NTOT 45088768        // OUTN * INN
#define SPADU 40             // smem row stride in b16 units (64B data + 16B pad)

// GEMM pipeline config (bf16, BK=32 elems = 64B rows)
#define TILEB 10240          // bytes per array per stage (128 rows * 80B)
#define STGB  (2 * TILEB)    // A + B per stage
#define NSTG  4
#define GSMEM (NSTG * STGB)  // 81920
#define NTILES 2752          // 86 n-tiles * 32 m-tiles
#define PGRID  296           // persistent: 2 CTAs/SM * 148

// packed fp32x2 FMA (exact IEEE fp32 per lane; sm_100+)
#define PACK2(out, lo, hi) \
    asm("mov.b64 %0, {%1, %2};" : "=l"(out) : "f"(lo), "f"(hi))
#define UNPACK2(lo, hi, in) \
    asm("mov.b64 {%0, %1}, %2;" : "=f"(lo), "=f"(hi) : "l"(in))
#define FMA2(d, a, b) \
    asm("fma.rn.f32x2 %0, %1, %2, %0;" : "+l"(d) : "l"(a), "l"(b))

// ---------------- scratch (static device globals; no allocation) ----------------
__device__ float          g_wt[NTOT];          // transformed/clipped weights (fp32)
__device__ __nv_bfloat16  g_wqb[NTOT];         // int4-valued weights as bf16 (exact)
__device__ __nv_bfloat16  g_xab[MTOK * INN];   // int8-valued activations as bf16 (exact)
__device__ signed char    g_xq8[MTOK * INN];   // int8 activations (for corr path)
__device__ signed char    g_xq8T[INN * MTOK];  // transposed activations [k][m]
__device__ float          g_corr[NTOT];        // outlier correction [n][m]
__device__ float          g_wscale[OUTN];
__device__ float          g_ascale[MTOK];
__device__ float          g_rowabs[OUTN];
__device__ double         g_psum[OUTN];
__device__ double         g_psumsq[OUTN];
__device__ int            g_icnt;              // global outlier count (int atomic)
__device__ float          g_stats[4];          // [0]=mean, [1]=T=3*std

// ================ K0: transform (blocks 0..11007) + actq (blocks 11008..15103) ================
__global__ __launch_bounds__(256) void k_front(
    const float* __restrict__ W, const float* __restrict__ L,
    const float* __restrict__ R, const float* __restrict__ cmax,
    const float* __restrict__ cmin, const float* __restrict__ X)
{
    __shared__ double sAd[2048];   // 16KB, aliased as float sA[4096]
    __shared__ float  sL[4096];
    __shared__ float  sR[4096];
    float* sA = (float*)sAd;

    const int tid = threadIdx.x;

    if (blockIdx.x >= OUTN) {
        // ---- activation fake-quant for token t ----
        const int t = blockIdx.x - OUTN;
        if (t == 0 && tid == 0) g_icnt = 0;
        float* red = sL;
        const float* x = X + (size_t)t * INN;
        float4 vals[4];
        float la = 0.f;
        #pragma unroll
        for (int i = 0; i < 4; i++) {
            vals[i] = *(const float4*)&x[(tid + i * 256) * 4];
            la = fmaxf(la, fmaxf(fmaxf(fabsf(vals[i].x), fabsf(vals[i].y)),
                                 fmaxf(fabsf(vals[i].z), fabsf(vals[i].w))));
        }
        red[tid] = la;
        __syncthreads();
        for (int s = 128; s > 0; s >>= 1) {
            if (tid < s) red[tid] = fmaxf(red[tid], red[tid + s]);
            __syncthreads();
        }
        const float scale = red[0] / 127.0f + 1e-8f;
        if (tid == 0) g_ascale[t] = scale;
        signed char*   out8 = g_xq8 + (size_t)t * INN;
        __nv_bfloat16* outb = g_xab + (size_t)t * INN;
        #pragma unroll
        for (int i = 0; i < 4; i++) {
            float4 v = vals[i];
            float q0 = fminf(fmaxf(rintf(v.x / scale), -127.f), 127.f);
            float q1 = fminf(fmaxf(rintf(v.y / scale), -127.f), 127.f);
            float q2 = fminf(fmaxf(rintf(v.z / scale), -127.f), 127.f);
            float q3 = fminf(fmaxf(rintf(v.w / scale), -127.f), 127.f);
            union { int w; signed char b[4]; } p;
            p.b[0] = (signed char)q0; p.b[1] = (signed char)q1;
            p.b[2] = (signed char)q2; p.b[3] = (signed char)q3;
            *(int*)&out8[(tid + i * 256) * 4] = p.w;
            __nv_bfloat16 qb[4];
            qb[0] = __float2bfloat16_rn(q0); qb[1] = __float2bfloat16_rn(q1);
            qb[2] = __float2bfloat16_rn(q2); qb[3] = __float2bfloat16_rn(q3);
            *(uint2*)&outb[(tid + i * 256) * 4] = *(uint2*)qb;
        }
        return;
    }

    // ---- kronecker transform + clip + row stats for row o (packed f32x2 FMAs) ----
    const int o = blockIdx.x;
    const int u = tid >> 4;
    const int v = tid & 15;

    const float* Wo = W + (size_t)o * INN;
    for (int i = tid; i < 4096; i += 256) { sA[i] = Wo[i]; sL[i] = L[i]; sR[i] = R[i]; }
    __syncthreads();

    // t[a,d] = sum_b W[a,b] * R[b,d]
    unsigned long long acc2[4][2];
    #pragma unroll
    for (int j = 0; j < 4; j++) { acc2[j][0] = 0ull; acc2[j][1] = 0ull; }

    for (int b = 0; b < 64; b++) {
        float4 rr = *(const float4*)&sR[(b << 6) + (v << 2)];
        unsigned long long rr01, rr23;
        PACK2(rr01, rr.x, rr.y);
        PACK2(rr23, rr.z, rr.w);
        #pragma unroll
        for (int j = 0; j < 4; j++) {
            float wrj = sA[(((u << 2) + j) << 6) + b];
            unsigned long long wp;
            PACK2(wp, wrj, wrj);
            FMA2(acc2[j][0], wp, rr01);
            FMA2(acc2[j][1], wp, rr23);
        }
    }
    __syncthreads();
    #pragma unroll
    for (int j = 0; j < 4; j++) {
        float a0, a1, a2, a3;
        UNPACK2(a0, a1, acc2[j][0]);
        UNPACK2(a2, a3, acc2[j][1]);
        *(float4*)&sA[(((u << 2) + j) << 6) + (v << 2)] = make_float4(a0, a1, a2, a3);
    }
    __syncthreads();

    // out[c,d] = sum_a L[a,c] * t[a,d]
    unsigned long long vv2[4][2];
    #pragma unroll
    for (int j = 0; j < 4; j++) { vv2[j][0] = 0ull; vv2[j][1] = 0ull; }

    for (int a = 0; a < 64; a++) {
        float4 td = *(const float4*)&sA[(a << 6) + (v << 2)];
        float4 lc = *(const float4*)&sL[(a << 6) + (u << 2)];
        unsigned long long td01, td23;
        PACK2(td01, td.x, td.y);
        PACK2(td23, td.z, td.w);
        float lcr[4] = {lc.x, lc.y, lc.z, lc.w};
        #pragma unroll
        for (int j = 0; j < 4; j++) {
            unsigned long long lp;
            PACK2(lp, lcr[j], lcr[j]);
            FMA2(vv2[j][0], lp, td01);
            FMA2(vv2[j][1], lp, td23);
        }
    }

    float vv[4][4];
    #pragma unroll
    for (int j = 0; j < 4; j++) {
        UNPACK2(vv[j][0], vv[j][1], vv2[j][0]);
        UNPACK2(vv[j][2], vv[j][3], vv2[j][1]);
    }

    float lmin = 3.4e38f, lmax = -3.4e38f;
    #pragma unroll
    for (int j = 0; j < 4; j++)
        #pragma unroll
        for (int l = 0; l < 4; l++) { lmin = fminf(lmin, vv[j][l]); lmax = fmaxf(lmax, vv[j][l]); }

    __syncthreads();
    sR[tid] = lmin; sR[256 + tid] = lmax;
    __syncthreads();
    for (int s = 128; s > 0; s >>= 1) {
        if (tid < s) {
            sR[tid]       = fminf(sR[tid], sR[tid + s]);
            sR[256 + tid] = fmaxf(sR[256 + tid], sR[256 + tid + s]);
        }
        __syncthreads();
    }
    const float rmin = sR[0], rmax = sR[256];
    const float lo = rmin * (1.f / (1.f + expf(-cmin[o])));
    const float hi = rmax * (1.f / (1.f + expf(-cmax[o])));

    float la = 0.f; double ls = 0.0, lss = 0.0;
    #pragma unroll
    for (int j = 0; j < 4; j++)
        #pragma unroll
        for (int l = 0; l < 4; l++) {
            float w = fminf(fmaxf(vv[j][l], lo), hi);
            vv[j][l] = w;
            la = fmaxf(la, fabsf(w));
            ls += (double)w;
            lss += (double)w * (double)w;
        }

    __syncthreads();
    sAd[tid] = ls; sAd[256 + tid] = lss; sR[tid] = la;
    __syncthreads();
    for (int s = 128; s > 0; s >>= 1) {
        if (tid < s) {
            sAd[tid]       += sAd[tid + s];
            sAd[256 + tid] += sAd[256 + tid + s];
            sR[tid] = fmaxf(sR[tid], sR[tid + s]);
        }
        __syncthreads();
    }
    if (tid == 0) { g_psum[o] = sAd[0]; g_psumsq[o] = sAd[256]; g_rowabs[o] = sR[0]; }

    float* outp = g_wt + (size_t)o * INN;
    #pragma unroll
    for (int j = 0; j < 4; j++)
        *(float4*)&outp[(((u << 2) + j) << 6) + (v << 2)] =
            make_float4(vv[j][0], vv[j][1], vv[j][2], vv[j][3]);
}

// ================ K1: stats+count (blocks 0..1023) + transpose xT (blocks 1024..5119) ================
__global__ __launch_bounds__(256) void k_mid()
{
    __shared__ double ds[512];
    __shared__ int    sc[256];
    __shared__ signed char ts[64 * 65];

    const int tid = threadIdx.x;

    if (blockIdx.x >= 1024) {
        int b2 = blockIdx.x - 1024;
        int k0 = (b2 & 63) * 64, m0 = (b2 >> 6) * 64;
        int r  = tid >> 2;
        int c4 = (tid & 3) * 16;
        union { int4 v; signed char b[16]; } u;
        u.v = *(const int4*)(g_xq8 + (size_t)(m0 + r) * INN + k0 + c4);
        #pragma unroll
        for (int i = 0; i < 16; i++) ts[r * 65 + c4 + i] = u.b[i];
        __syncthreads();
        #pragma unroll
        for (int i = 0; i < 16; i++) u.b[i] = ts[(c4 + i) * 65 + r];
        *(int4*)(g_xq8T + (size_t)(k0 + r) * MTOK + m0 + c4) = u.v;
        return;
    }

    double s = 0.0, ss = 0.0;
    for (int i = tid; i < OUTN; i += 256) { s += g_psum[i]; ss += g_psumsq[i]; }
    ds[tid] = s; ds[256 + tid] = ss;
    __syncthreads();
    for (int st = 128; st > 0; st >>= 1) {
        if (tid < st) { ds[tid] += ds[tid + st]; ds[256 + tid] += ds[256 + tid + st]; }
        __syncthreads();
    }
    double mean_d = ds[0] / (double)NTOT;
    double var    = ds[256] / (double)NTOT - mean_d * mean_d;
    if (var < 0.0) var = 0.0;
    const float mean = (float)mean_d;
    const float T    = (float)(3.0 * sqrt(var));
    if (blockIdx.x == 0 && tid == 0) { g_stats[0] = mean; g_stats[1] = T; }

    int cnt = 0;
    size_t stride = (size_t)1024 * 256 * 4;
    for (size_t i = ((size_t)blockIdx.x * 256 + tid) * 4; i < (size_t)NTOT; i += stride) {
        float4 w4 = *(const float4*)(g_wt + i);
        cnt += (fabsf(w4.x - mean) > T) + (fabsf(w4.y - mean) > T)
             + (fabsf(w4.z - mean) > T) + (fabsf(w4.w - mean) > T);
    }
    sc[tid] = cnt;
    __syncthreads();
    for (int st = 128; st > 0; st >>= 1) {
        if (tid < st) sc[tid] += sc[tid + st];
        __syncthreads();
    }
    if (tid == 0) atomicAdd(&g_icnt, sc[0]);
}

// ================ K2: per-row quantize (-> bf16 q) + sparse list (smem) + corr row ================
__global__ __launch_bounds__(256) void k_wfinal2()
{
    __shared__ int            scnt[256];
    __shared__ unsigned short sk[4096];
    __shared__ float          sdl[4096];

    const int o   = blockIdx.x;
    const int tid = threadIdx.x;
    const float a1 = 0.01f;
    const float T = g_stats[1];
    const float frac = (float)g_icnt / (float)NTOT;
    const bool like = (frac > 1e-4f && frac < 0.05f);

    float ra = g_rowabs[o];
    float m = (like && ra > T) ? (T + (ra - T) * a1) : ra;   // fold monotone in |w|
    float scale = m / 7.0f + 1e-8f;
    if (tid == 0) g_wscale[o] = scale;

    const float* wrow = g_wt + (size_t)o * INN;

    __nv_bfloat16 qb[16];
    float dl[16];
    unsigned tagmask = 0;
    int cnt = 0;

    #pragma unroll
    for (int g = 0; g < 4; g++) {
        float4 w4 = *(const float4*)(wrow + tid * 16 + g * 4);
        float wv[4] = {w4.x, w4.y, w4.z, w4.w};
        #pragma unroll
        for (int e = 0; e < 4; e++) {
            int idx = g * 4 + e;
            float w = wv[e];
            bool tg = like && (fabsf(w) > T);
            float win = tg ? copysignf(T + (fabsf(w) - T) * a1, w) : w;
            float q = fminf(fmaxf(rintf(win / scale), -7.f), 7.f);
            float wq = q * scale;
            float wfin = tg ? copysignf(T + (fabsf(wq) - T) / a1, w) : wq;
            qb[idx] = __float2bfloat16_rn(q);   // exact small integer
            dl[idx] = wfin - wq;                // zero for untagged
            if (tg) { tagmask |= (1u << idx); cnt++; }
        }
    }
    {
        __nv_bfloat16* wb = g_wqb + (size_t)o * INN + tid * 16;
        *(uint4*)wb       = *(uint4*)&qb[0];
        *(uint4*)(wb + 8) = *(uint4*)&qb[8];
    }

    scnt[tid] = cnt;
    __syncthreads();
    for (int s = 1; s < 256; s <<= 1) {
        int v = 0;
        if (tid >= s) v = scnt[tid - s];
        __syncthreads();
        if (tid >= s) scnt[tid] += v;
        __syncthreads();
    }
    int off = scnt[tid] - cnt;
    __syncthreads();
    const int total = scnt[255];

    #pragma unroll
    for (int idx = 0; idx < 16; idx++) {
        if (tagmask & (1u << idx)) {
            sk[off]  = (unsigned short)(tid * 16 + idx);
            sdl[off] = dl[idx];
            off++;
        }
    }
    __syncthreads();

    float cv[16];
    #pragma unroll
    for (int i = 0; i < 16; i++) cv[i] = 0.f;
    for (int t = 0; t < total; t++) {
        const signed char* col = g_xq8T + (size_t)sk[t] * MTOK;
        float d = sdl[t];
        #pragma unroll
        for (int i = 0; i < 16; i++)
            cv[i] += (float)col[tid + i * 256] * d;
    }
    float* outc = g_corr + (size_t)o * MTOK;
    #pragma unroll
    for (int i = 0; i < 16; i++) outc[tid + i * 256] = cv[i];
}

// ================ K3: persistent bf16 HMMA GEMM, 64x64 warp tiles, cg loads ================
__device__ __forceinline__ void cpasync16(unsigned saddr, const void* g)
{
    asm volatile("cp.async.cg.shared.global [%0], [%1], 16;\n" :: "r"(saddr), "l"(g));
}
__device__ __forceinline__ void ldsm4(unsigned* r, unsigned saddr)
{
    asm volatile("ldmatrix.sync.aligned.m8n8.x4.shared.b16 {%0,%1,%2,%3}, [%4];"
                 : "=r"(r[0]), "=r"(r[1]), "=r"(r[2]), "=r"(r[3]) : "r"(saddr));
}
__device__ __forceinline__ void mma16816(float* d, const unsigned* a, unsigned b0, unsigned b1)
{
    asm volatile("mma.sync.aligned.m16n8k16.row.col.f32.bf16.bf16.f32 "
                 "{%0,%1,%2,%3}, {%4,%5,%6,%7}, {%8,%9}, {%0,%1,%2,%3};"
                 : "+f"(d[0]), "+f"(d[1]), "+f"(d[2]), "+f"(d[3])
                 : "r"(a[0]), "r"(a[1]), "r"(a[2]), "r"(a[3]), "r"(b0), "r"(b1));
}

__global__ __launch_bounds__(128, 2) void k_gemm_bf(const float* __restrict__ bias,
                                                    float* __restrict__ C)
{
    extern __shared__ char dsm[];

    const int tid  = threadIdx.x;
    const int lane = tid & 31;
    const int wid  = tid >> 5;      // 0..3
    const int wm   = wid & 1;       // 2 warps in M
    const int wn   = wid >> 1;      // 2 warps in N

    const int lrow  = tid >> 2;          // 0..31
    const int lcolu = (tid & 3) * 8;     // element col 0,8,16,24

    const int KITERS = INN / 32;   // 128

    for (int t = blockIdx.x; t < NTILES; t += gridDim.x) {
        const int bm = (t & 31) * 128;   // m inner: A tiles cycle within L2
        const int bn = (t >> 5) * 128;

        const __nv_bfloat16* Abase = g_xab + (size_t)bm * INN;
        const __nv_bfloat16* Bbase = g_wqb + (size_t)bn * INN;

        float acc[4][8][4];
        #pragma unroll
        for (int i = 0; i < 4; i++)
            #pragma unroll
            for (int j = 0; j < 8; j++)
                #pragma unroll
                for (int l = 0; l < 4; l++) acc[i][j][l] = 0.f;

        auto fill = [&](int it) {
            int s = it & 3;
            int k = it * 32;
            unsigned sA = (unsigned)__cvta_generic_to_shared(dsm + s * STGB);
            unsigned sB = sA + TILEB;
            #pragma unroll
            for (int i = 0; i < 4; i++) {
                int row = lrow + i * 32;
                cpasync16(sA + (row * SPADU + lcolu) * 2,
                          Abase + (size_t)row * INN + k + lcolu);
                cpasync16(sB + (row * SPADU + lcolu) * 2,
                          Bbase + (size_t)row * INN + k + lcolu);
            }
            asm volatile("cp.async.commit_group;\n");
        };

        fill(0); fill(1); fill(2);

        for (int it = 0; it < KITERS; ++it) {
            if (it < KITERS - 2)       asm volatile("cp.async.wait_group 2;\n");
            else if (it == KITERS - 2) asm volatile("cp.async.wait_group 1;\n");
            else                       asm volatile("cp.async.wait_group 0;\n");
            __syncthreads();

            if (it + 3 < KITERS) fill(it + 3);

            unsigned tb = (unsigned)__cvta_generic_to_shared(dsm + (it & 3) * STGB);
            unsigned tA = tb, tB = tb + TILEB;

            #pragma unroll
            for (int ks = 0; ks < 2; ks++) {
                unsigned afr[4][4], bfr[4][4];
                int arow = wm * 64 + (lane & 15);
                int acol = ks * 16 + (lane >> 4) * 8;
                #pragma unroll
                for (int mb = 0; mb < 4; mb++)
                    ldsm4(afr[mb], tA + ((arow + mb * 16) * SPADU + acol) * 2);
                int brow = wn * 64 + (lane & 7) + ((lane >> 4) & 1) * 8;
                int bcol = ks * 16 + ((lane >> 3) & 1) * 8;
                #pragma unroll
                for (int nb = 0; nb < 4; nb++)
                    ldsm4(bfr[nb], tB + ((brow + nb * 16) * SPADU + bcol) * 2);
                #pragma unroll
                for (int mb = 0; mb < 4; mb++)
                    #pragma unroll
                    for (int f = 0; f < 8; f++)
                        mma16816(acc[mb][f], afr[mb],
                                 bfr[f >> 1][(f & 1) * 2], bfr[f >> 1][(f & 1) * 2 + 1]);
            }
        }

        // ---- epilogue: out = as_m * (ws_n * acc + corr[n][m]) + bias ----
        #pragma unroll
        for (int mb = 0; mb < 4; mb++) {
            int m0 = bm + wm * 64 + mb * 16 + (lane >> 2);
            float as0 = g_ascale[m0];
            float as1 = g_ascale[m0 + 8];
            #pragma unroll
            for (int f = 0; f < 8; f++) {
                int gn = bn + wn * 64 + f * 8 + (lane & 3) * 2;
                float ws0 = g_wscale[gn], ws1 = g_wscale[gn + 1];
                float b0 = bias[gn], b1 = bias[gn + 1];
                const float* c0 = g_corr + (size_t)gn * MTOK;
                const float* c1 = c0 + MTOK;
                float2 o0 = make_float2(
                    as0 * (ws0 * acc[mb][f][0] + c0[m0]) + b0,
                    as0 * (ws1 * acc[mb][f][1] + c1[m0]) + b1);
                float2 o1 = make_float2(
                    as1 * (ws0 * acc[mb][f][2] + c0[m0 + 8]) + b0,
                    as1 * (ws1 * acc[mb][f][3] + c1[m0 + 8]) + b1);
                *(float2*)(C + (size_t)m0 * OUTN + gn)       = o0;
                *(float2*)(C + (size_t)(m0 + 8) * OUTN + gn) = o1;
            }
        }
        __syncthreads();   // smem safe for next tile's fills
    }
}

// ---------------- launch ----------------
extern "C" void kernel_launch(void* const* d_in, const int* in_sizes, int n_in,
                              void* d_out, int out_size)
{
    const float* hs   = (const float*)d_in[0];  // (2,2048,4096)
    const float* w    = (const float*)d_in[1];  // (11008,4096)
    const float* bias = (const float*)d_in[2];  // (11008)
    const float* tl   = (const float*)d_in[3];  // (64,64)
    const float* tr   = (const float*)d_in[4];  // (64,64)
    const float* cmax = (const float*)d_in[5];  // (11008,1)
    const float* cmin = (const float*)d_in[6];  // (11008,1)
    float* out = (float*)d_out;

    static bool attr_set = false;
    if (!attr_set) {
        cudaFuncSetAttribute(k_gemm_bf, cudaFuncAttributeMaxDynamicSharedMemorySize, GSMEM);
        attr_set = true;
    }

    k_front<<<OUTN + MTOK, 256>>>(w, tl, tr, cmax, cmin, hs);   // launch 0
    k_mid<<<1024 + 4096, 256>>>();                              // launch 1
    k_wfinal2<<<OUTN, 256>>>();                                 // launch 2
    k_gemm_bf<<<PGRID, 128, GSMEM>>>(bias, out);                // launch 3
}

// round 12
// speedup vs baseline: 1.8353x; 1.0013x over previous
#include <cuda_runtime.h>
#include <cuda_bf16.h>
#include <math.h>

#define OUTN 11008
#define INN  4096
#define MTOK 4096            // 2 * 2048 tokens
#define NTOT 45088768        // OUTN * INN
#define SPADU 40             // smem row stride in b16 units (64B data + 16B pad)

// GEMM pipeline config (bf16, BK=32 elems = 64B rows)
#define TILEB 10240          // bytes per array per stage (128 rows * 80B)
#define STGB  (2 * TILEB)    // A + B per stage
#define NSTG  4
#define GSMEM (NSTG * STGB)  // 81920
#define NTILES 2752          // 86 n-tiles * 32 m-tiles
#define PGRID  296           // persistent: 2 CTAs/SM * 148

// packed fp32x2 FMA (exact IEEE fp32 per lane; sm_100+)
#define PACK2(out, lo, hi) \
    asm("mov.b64 %0, {%1, %2};" : "=l"(out) : "f"(lo), "f"(hi))
#define UNPACK2(lo, hi, in) \
    asm("mov.b64 {%0, %1}, %2;" : "=f"(lo), "=f"(hi) : "l"(in))
#define FMA2(d, a, b) \
    asm("fma.rn.f32x2 %0, %1, %2, %0;" : "+l"(d) : "l"(a), "l"(b))

// ---------------- scratch (static device globals; no allocation) ----------------
__device__ float          g_wt[NTOT];          // transformed/clipped weights (fp32)
__device__ __nv_bfloat16  g_wqb[NTOT];         // int4-valued weights as bf16 (exact)
__device__ __nv_bfloat16  g_xab[MTOK * INN];   // int8-valued activations as bf16 (exact)
__device__ signed char    g_xq8[MTOK * INN];   // int8 activations (for corr path)
__device__ signed char    g_xq8T[INN * MTOK];  // transposed activations [k][m]
__device__ float          g_corr[NTOT];        // outlier correction [n][m]
__device__ float          g_wscale[OUTN];
__device__ float          g_ascale[MTOK];
__device__ float          g_rowabs[OUTN];
__device__ double         g_psum[OUTN];
__device__ double         g_psumsq[OUTN];
__device__ int            g_icnt;              // global outlier count (int atomic)
__device__ float          g_stats[4];          // [0]=mean, [1]=T=3*std

// ================ K0: transform (blocks 0..11007) + actq (blocks 11008..15103) ================
__global__ __launch_bounds__(256) void k_front(
    const float* __restrict__ W, const float* __restrict__ L,
    const float* __restrict__ R, const float* __restrict__ cmax,
    const float* __restrict__ cmin, const float* __restrict__ X)
{
    __shared__ double sAd[2048];   // 16KB, aliased as float sA[4096]
    __shared__ float  sL[4096];
    __shared__ float  sR[4096];
    float* sA = (float*)sAd;

    const int tid = threadIdx.x;

    if (blockIdx.x >= OUTN) {
        // ---- activation fake-quant for token t ----
        const int t = blockIdx.x - OUTN;
        if (t == 0 && tid == 0) g_icnt = 0;
        float* red = sL;
        const float* x = X + (size_t)t * INN;
        float4 vals[4];
        float la = 0.f;
        #pragma unroll
        for (int i = 0; i < 4; i++) {
            vals[i] = *(const float4*)&x[(tid + i * 256) * 4];
            la = fmaxf(la, fmaxf(fmaxf(fabsf(vals[i].x), fabsf(vals[i].y)),
                                 fmaxf(fabsf(vals[i].z), fabsf(vals[i].w))));
        }
        red[tid] = la;
        __syncthreads();
        for (int s = 128; s > 0; s >>= 1) {
            if (tid < s) red[tid] = fmaxf(red[tid], red[tid + s]);
            __syncthreads();
        }
        const float scale = red[0] / 127.0f + 1e-8f;
        if (tid == 0) g_ascale[t] = scale;
        signed char*   out8 = g_xq8 + (size_t)t * INN;
        __nv_bfloat16* outb = g_xab + (size_t)t * INN;
        #pragma unroll
        for (int i = 0; i < 4; i++) {
            float4 v = vals[i];
            float q0 = fminf(fmaxf(rintf(v.x / scale), -127.f), 127.f);
            float q1 = fminf(fmaxf(rintf(v.y / scale), -127.f), 127.f);
            float q2 = fminf(fmaxf(rintf(v.z / scale), -127.f), 127.f);
            float q3 = fminf(fmaxf(rintf(v.w / scale), -127.f), 127.f);
            union { int w; signed char b[4]; } p;
            p.b[0] = (signed char)q0; p.b[1] = (signed char)q1;
            p.b[2] = (signed char)q2; p.b[3] = (signed char)q3;
            *(int*)&out8[(tid + i * 256) * 4] = p.w;
            __nv_bfloat16 qb[4];
            qb[0] = __float2bfloat16_rn(q0); qb[1] = __float2bfloat16_rn(q1);
            qb[2] = __float2bfloat16_rn(q2); qb[3] = __float2bfloat16_rn(q3);
            *(uint2*)&outb[(tid + i * 256) * 4] = *(uint2*)qb;
        }
        return;
    }

    // ---- kronecker transform + clip + row stats for row o (packed f32x2 FMAs) ----
    const int o = blockIdx.x;
    const int u = tid >> 4;
    const int v = tid & 15;

    const float* Wo = W + (size_t)o * INN;
    for (int i = tid; i < 4096; i += 256) { sA[i] = Wo[i]; sL[i] = L[i]; sR[i] = R[i]; }
    __syncthreads();

    // t[a,d] = sum_b W[a,b] * R[b,d]
    unsigned long long acc2[4][2];
    #pragma unroll
    for (int j = 0; j < 4; j++) { acc2[j][0] = 0ull; acc2[j][1] = 0ull; }

    for (int b = 0; b < 64; b++) {
        float4 rr = *(const float4*)&sR[(b << 6) + (v << 2)];
        unsigned long long rr01, rr23;
        PACK2(rr01, rr.x, rr.y);
        PACK2(rr23, rr.z, rr.w);
        #pragma unroll
        for (int j = 0; j < 4; j++) {
            float wrj = sA[(((u << 2) + j) << 6) + b];
            unsigned long long wp;
            PACK2(wp, wrj, wrj);
            FMA2(acc2[j][0], wp, rr01);
            FMA2(acc2[j][1], wp, rr23);
        }
    }
    __syncthreads();
    #pragma unroll
    for (int j = 0; j < 4; j++) {
        float a0, a1, a2, a3;
        UNPACK2(a0, a1, acc2[j][0]);
        UNPACK2(a2, a3, acc2[j][1]);
        *(float4*)&sA[(((u << 2) + j) << 6) + (v << 2)] = make_float4(a0, a1, a2, a3);
    }
    __syncthreads();

    // out[c,d] = sum_a L[a,c] * t[a,d]
    unsigned long long vv2[4][2];
    #pragma unroll
    for (int j = 0; j < 4; j++) { vv2[j][0] = 0ull; vv2[j][1] = 0ull; }

    for (int a = 0; a < 64; a++) {
        float4 td = *(const float4*)&sA[(a << 6) + (v << 2)];
        float4 lc = *(const float4*)&sL[(a << 6) + (u << 2)];
        unsigned long long td01, td23;
        PACK2(td01, td.x, td.y);
        PACK2(td23, td.z, td.w);
        float lcr[4] = {lc.x, lc.y, lc.z, lc.w};
        #pragma unroll
        for (int j = 0; j < 4; j++) {
            unsigned long long lp;
            PACK2(lp, lcr[j], lcr[j]);
            FMA2(vv2[j][0], lp, td01);
            FMA2(vv2[j][1], lp, td23);
        }
    }

    float vv[4][4];
    #pragma unroll
    for (int j = 0; j < 4; j++) {
        UNPACK2(vv[j][0], vv[j][1], vv2[j][0]);
        UNPACK2(vv[j][2], vv[j][3], vv2[j][1]);
    }

    float lmin = 3.4e38f, lmax = -3.4e38f;
    #pragma unroll
    for (int j = 0; j < 4; j++)
        #pragma unroll
        for (int l = 0; l < 4; l++) { lmin = fminf(lmin, vv[j][l]); lmax = fmaxf(lmax, vv[j][l]); }

    __syncthreads();
    sR[tid] = lmin; sR[256 + tid] = lmax;
    __syncthreads();
    for (int s = 128; s > 0; s >>= 1) {
        if (tid < s) {
            sR[tid]       = fminf(sR[tid], sR[tid + s]);
            sR[256 + tid] = fmaxf(sR[256 + tid], sR[256 + tid + s]);
        }
        __syncthreads();
    }
    const float rmin = sR[0], rmax = sR[256];
    const float lo = rmin * (1.f / (1.f + expf(-cmin[o])));
    const float hi = rmax * (1.f / (1.f + expf(-cmax[o])));

    float la = 0.f; double ls = 0.0, lss = 0.0;
    #pragma unroll
    for (int j = 0; j < 4; j++)
        #pragma unroll
        for (int l = 0; l < 4; l++) {
            float w = fminf(fmaxf(vv[j][l], lo), hi);
            vv[j][l] = w;
            la = fmaxf(la, fabsf(w));
            ls += (double)w;
            lss += (double)w * (double)w;
        }

    __syncthreads();
    sAd[tid] = ls; sAd[256 + tid] = lss; sR[tid] = la;
    __syncthreads();
    for (int s = 128; s > 0; s >>= 1) {
        if (tid < s) {
            sAd[tid]       += sAd[tid + s];
            sAd[256 + tid] += sAd[256 + tid + s];
            sR[tid] = fmaxf(sR[tid], sR[tid + s]);
        }
        __syncthreads();
    }
    if (tid == 0) { g_psum[o] = sAd[0]; g_psumsq[o] = sAd[256]; g_rowabs[o] = sR[0]; }

    float* outp = g_wt + (size_t)o * INN;
    #pragma unroll
    for (int j = 0; j < 4; j++)
        *(float4*)&outp[(((u << 2) + j) << 6) + (v << 2)] =
            make_float4(vv[j][0], vv[j][1], vv[j][2], vv[j][3]);
}

// ================ K1: stats+count (blocks 0..1023) + transpose xT (blocks 1024..5119) ================
__global__ __launch_bounds__(256) void k_mid()
{
    __shared__ double ds[512];
    __shared__ int    sc[256];
    __shared__ signed char ts[64 * 65];

    const int tid = threadIdx.x;

    if (blockIdx.x >= 1024) {
        int b2 = blockIdx.x - 1024;
        int k0 = (b2 & 63) * 64, m0 = (b2 >> 6) * 64;
        int r  = tid >> 2;
        int c4 = (tid & 3) * 16;
        union { int4 v; signed char b[16]; } u;
        u.v = *(const int4*)(g_xq8 + (size_t)(m0 + r) * INN + k0 + c4);
        #pragma unroll
        for (int i = 0; i < 16; i++) ts[r * 65 + c4 + i] = u.b[i];
        __syncthreads();
        #pragma unroll
        for (int i = 0; i < 16; i++) u.b[i] = ts[(c4 + i) * 65 + r];
        *(int4*)(g_xq8T + (size_t)(k0 + r) * MTOK + m0 + c4) = u.v;
        return;
    }

    double s = 0.0, ss = 0.0;
    for (int i = tid; i < OUTN; i += 256) { s += g_psum[i]; ss += g_psumsq[i]; }
    ds[tid] = s; ds[256 + tid] = ss;
    __syncthreads();
    for (int st = 128; st > 0; st >>= 1) {
        if (tid < st) { ds[tid] += ds[tid + st]; ds[256 + tid] += ds[256 + tid + st]; }
        __syncthreads();
    }
    double mean_d = ds[0] / (double)NTOT;
    double var    = ds[256] / (double)NTOT - mean_d * mean_d;
    if (var < 0.0) var = 0.0;
    const float mean = (float)mean_d;
    const float T    = (float)(3.0 * sqrt(var));
    if (blockIdx.x == 0 && tid == 0) { g_stats[0] = mean; g_stats[1] = T; }

    int cnt = 0;
    size_t stride = (size_t)1024 * 256 * 4;
    for (size_t i = ((size_t)blockIdx.x * 256 + tid) * 4; i < (size_t)NTOT; i += stride) {
        float4 w4 = *(const float4*)(g_wt + i);
        cnt += (fabsf(w4.x - mean) > T) + (fabsf(w4.y - mean) > T)
             + (fabsf(w4.z - mean) > T) + (fabsf(w4.w - mean) > T);
    }
    sc[tid] = cnt;
    __syncthreads();
    for (int st = 128; st > 0; st >>= 1) {
        if (tid < st) sc[tid] += sc[tid + st];
        __syncthreads();
    }
    if (tid == 0) atomicAdd(&g_icnt, sc[0]);
}

// ================ K2: per-row quantize (-> bf16 q) + sparse list (smem) + corr row ================
__global__ __launch_bounds__(256) void k_wfinal2()
{
    __shared__ int            scnt[256];
    __shared__ unsigned short sk[4096];
    __shared__ float          sdl[4096];

    const int o   = blockIdx.x;
    const int tid = threadIdx.x;
    const float a1 = 0.01f;
    const float T = g_stats[1];
    const float frac = (float)g_icnt / (float)NTOT;
    const bool like = (frac > 1e-4f && frac < 0.05f);

    float ra = g_rowabs[o];
    float m = (like && ra > T) ? (T + (ra - T) * a1) : ra;   // fold monotone in |w|
    float scale = m / 7.0f + 1e-8f;
    if (tid == 0) g_wscale[o] = scale;

    const float* wrow = g_wt + (size_t)o * INN;

    __nv_bfloat16 qb[16];
    float dl[16];
    unsigned tagmask = 0;
    int cnt = 0;

    #pragma unroll
    for (int g = 0; g < 4; g++) {
        float4 w4 = *(const float4*)(wrow + tid * 16 + g * 4);
        float wv[4] = {w4.x, w4.y, w4.z, w4.w};
        #pragma unroll
        for (int e = 0; e < 4; e++) {
            int idx = g * 4 + e;
            float w = wv[e];
            bool tg = like && (fabsf(w) > T);
            float win = tg ? copysignf(T + (fabsf(w) - T) * a1, w) : w;
            float q = fminf(fmaxf(rintf(win / scale), -7.f), 7.f);
            float wq = q * scale;
            float wfin = tg ? copysignf(T + (fabsf(wq) - T) / a1, w) : wq;
            qb[idx] = __float2bfloat16_rn(q);   // exact small integer
            dl[idx] = wfin - wq;                // zero for untagged
            if (tg) { tagmask |= (1u << idx); cnt++; }
        }
    }
    {
        __nv_bfloat16* wb = g_wqb + (size_t)o * INN + tid * 16;
        *(uint4*)wb       = *(uint4*)&qb[0];
        *(uint4*)(wb + 8) = *(uint4*)&qb[8];
    }

    scnt[tid] = cnt;
    __syncthreads();
    for (int s = 1; s < 256; s <<= 1) {
        int v = 0;
        if (tid >= s) v = scnt[tid - s];
        __syncthreads();
        if (tid >= s) scnt[tid] += v;
        __syncthreads();
    }
    int off = scnt[tid] - cnt;
    __syncthreads();
    const int total = scnt[255];

    #pragma unroll
    for (int idx = 0; idx < 16; idx++) {
        if (tagmask & (1u << idx)) {
            sk[off]  = (unsigned short)(tid * 16 + idx);
            sdl[off] = dl[idx];
            off++;
        }
    }
    __syncthreads();

    float cv[16];
    #pragma unroll
    for (int i = 0; i < 16; i++) cv[i] = 0.f;
    for (int t = 0; t < total; t++) {
        const signed char* col = g_xq8T + (size_t)sk[t] * MTOK;
        float d = sdl[t];
        #pragma unroll
        for (int i = 0; i < 16; i++)
            cv[i] += (float)col[tid + i * 256] * d;
    }
    float* outc = g_corr + (size_t)o * MTOK;
    #pragma unroll
    for (int i = 0; i < 16; i++) outc[tid + i * 256] = cv[i];
}

// ================ K3: persistent bf16 HMMA GEMM, batched fragment loads ================
__device__ __forceinline__ void cpasync16(unsigned saddr, const void* g)
{
    asm volatile("cp.async.cg.shared.global [%0], [%1], 16;\n" :: "r"(saddr), "l"(g));
}
__device__ __forceinline__ void ldsm4(unsigned* r, unsigned saddr)
{
    asm volatile("ldmatrix.sync.aligned.m8n8.x4.shared.b16 {%0,%1,%2,%3}, [%4];"
                 : "=r"(r[0]), "=r"(r[1]), "=r"(r[2]), "=r"(r[3]) : "r"(saddr));
}
__device__ __forceinline__ void mma16816(float* d, const unsigned* a, unsigned b0, unsigned b1)
{
    asm volatile("mma.sync.aligned.m16n8k16.row.col.f32.bf16.bf16.f32 "
                 "{%0,%1,%2,%3}, {%4,%5,%6,%7}, {%8,%9}, {%0,%1,%2,%3};"
                 : "+f"(d[0]), "+f"(d[1]), "+f"(d[2]), "+f"(d[3])
                 : "r"(a[0]), "r"(a[1]), "r"(a[2]), "r"(a[3]), "r"(b0), "r"(b1));
}

__global__ __launch_bounds__(128, 2) void k_gemm_bf(const float* __restrict__ bias,
                                                    float* __restrict__ C)
{
    extern __shared__ char dsm[];

    const int tid  = threadIdx.x;
    const int lane = tid & 31;
    const int wid  = tid >> 5;      // 0..3
    const int wm   = wid & 1;       // 2 warps in M
    const int wn   = wid >> 1;      // 2 warps in N

    const int lrow  = tid >> 2;          // 0..31
    const int lcolu = (tid & 3) * 8;     // element col 0,8,16,24

    const int KITERS = INN / 32;   // 128

    // precomputed fragment row/col offsets
    const int arow = wm * 64 + (lane & 15);
    const int acol0 = (lane >> 4) * 8;
    const int brow = wn * 64 + (lane & 7) + ((lane >> 4) & 1) * 8;
    const int bcol0 = ((lane >> 3) & 1) * 8;

    for (int t = blockIdx.x; t < NTILES; t += gridDim.x) {
        const int bm = (t & 31) * 128;   // m inner: A tiles cycle within L2
        const int bn = (t >> 5) * 128;

        const __nv_bfloat16* Abase = g_xab + (size_t)bm * INN;
        const __nv_bfloat16* Bbase = g_wqb + (size_t)bn * INN;

        float acc[4][8][4];
        #pragma unroll
        for (int i = 0; i < 4; i++)
            #pragma unroll
            for (int j = 0; j < 8; j++)
                #pragma unroll
                for (int l = 0; l < 4; l++) acc[i][j][l] = 0.f;

        auto fill = [&](int it) {
            int s = it & 3;
            int k = it * 32;
            unsigned sA = (unsigned)__cvta_generic_to_shared(dsm + s * STGB);
            unsigned sB = sA + TILEB;
            #pragma unroll
            for (int i = 0; i < 4; i++) {
                int row = lrow + i * 32;
                cpasync16(sA + (row * SPADU + lcolu) * 2,
                          Abase + (size_t)row * INN + k + lcolu);
                cpasync16(sB + (row * SPADU + lcolu) * 2,
                          Bbase + (size_t)row * INN + k + lcolu);
            }
            asm volatile("cp.async.commit_group;\n");
        };

        fill(0); fill(1); fill(2);

        for (int it = 0; it < KITERS; ++it) {
            if (it < KITERS - 2)       asm volatile("cp.async.wait_group 2;\n");
            else if (it == KITERS - 2) asm volatile("cp.async.wait_group 1;\n");
            else                       asm volatile("cp.async.wait_group 0;\n");
            __syncthreads();

            if (it + 3 < KITERS) fill(it + 3);

            unsigned tb = (unsigned)__cvta_generic_to_shared(dsm + (it & 3) * STGB);
            unsigned tA = tb, tB = tb + TILEB;

            // ---- batch ALL fragment loads for both ks phases up front ----
            unsigned afr[2][4][4], bfr[2][4][4];
            #pragma unroll
            for (int ks = 0; ks < 2; ks++) {
                int acol = ks * 16 + acol0;
                #pragma unroll
                for (int mb = 0; mb < 4; mb++)
                    ldsm4(afr[ks][mb], tA + ((arow + mb * 16) * SPADU + acol) * 2);
            }
            #pragma unroll
            for (int ks = 0; ks < 2; ks++) {
                int bcol = ks * 16 + bcol0;
                #pragma unroll
                for (int nb = 0; nb < 4; nb++)
                    ldsm4(bfr[ks][nb], tB + ((brow + nb * 16) * SPADU + bcol) * 2);
            }

            // ---- then all MMAs (operands resolve while LSU drains) ----
            #pragma unroll
            for (int ks = 0; ks < 2; ks++)
                #pragma unroll
                for (int mb = 0; mb < 4; mb++)
                    #pragma unroll
                    for (int f = 0; f < 8; f++)
                        mma16816(acc[mb][f], afr[ks][mb],
                                 bfr[ks][f >> 1][(f & 1) * 2],
                                 bfr[ks][f >> 1][(f & 1) * 2 + 1]);
        }

        // ---- epilogue: out = as_m * (ws_n * acc + corr[n][m]) + bias ----
        #pragma unroll
        for (int mb = 0; mb < 4; mb++) {
            int m0 = bm + wm * 64 + mb * 16 + (lane >> 2);
            float as0 = g_ascale[m0];
            float as1 = g_ascale[m0 + 8];
            #pragma unroll
            for (int f = 0; f < 8; f++) {
                int gn = bn + wn * 64 + f * 8 + (lane & 3) * 2;
                float ws0 = g_wscale[gn], ws1 = g_wscale[gn + 1];
                float b0 = bias[gn], b1 = bias[gn + 1];
                const float* c0 = g_corr + (size_t)gn * MTOK;
                const float* c1 = c0 + MTOK;
                float2 o0 = make_float2(
                    as0 * (ws0 * acc[mb][f][0] + c0[m0]) + b0,
                    as0 * (ws1 * acc[mb][f][1] + c1[m0]) + b1);
                float2 o1 = make_float2(
                    as1 * (ws0 * acc[mb][f][2] + c0[m0 + 8]) + b0,
                    as1 * (ws1 * acc[mb][f][3] + c1[m0 + 8]) + b1);
                *(float2*)(C + (size_t)m0 * OUTN + gn)       = o0;
                *(float2*)(C + (size_t)(m0 + 8) * OUTN + gn) = o1;
            }
        }
        __syncthreads();   // smem safe for next tile's fills
    }
}

// ---------------- launch ----------------
extern "C" void kernel_launch(void* const* d_in, const int* in_sizes, int n_in,
                              void* d_out, int out_size)
{
    const float* hs   = (const float*)d_in[0];  // (2,2048,4096)
    const float* w    = (const float*)d_in[1];  // (11008,4096)
    const float* bias = (const float*)d_in[2];  // (11008)
    const float* tl   = (const float*)d_in[3];  // (64,64)
    const float* tr   = (const float*)d_in[4];  // (64,64)
    const float* cmax = (const float*)d_in[5];  // (11008,1)
    const float* cmin = (const float*)d_in[6];  // (11008,1)
    float* out = (float*)d_out;

    static bool attr_set = false;
    if (!attr_set) {
        cudaFuncSetAttribute(k_gemm_bf, cudaFuncAttributeMaxDynamicSharedMemorySize, GSMEM);
        attr_set = true;
    }

    k_front<<<OUTN + MTOK, 256>>>(w, tl, tr, cmax, cmin, hs);   // launch 0
    k_mid<<<1024 + 4096, 256>>>();                              // launch 1
    k_wfinal2<<<OUTN, 256>>>();                                 // launch 2
    k_gemm_bf<<<PGRID, 128, GSMEM>>>(bias, out);                // launch 3
}